// round 15
// baseline (speedup 1.0000x reference)
#include <cuda_runtime.h>
#include <cuda_bf16.h>
#include <cstdint>
#include <math.h>

#define Bb   8
#define Nn   1024
#define Dd   64
#define Hh   4
#define Cc   129
#define Kk   16
#define Mm   4096
#define ROWS 8192   // B*N

// ---------------- helpers ----------------
__device__ __forceinline__ uint32_t cvt_bf16x2(float hi, float lo) {
    uint32_t r;
    asm("cvt.rn.bf16x2.f32 %0, %1, %2;" : "=r"(r) : "f"(hi), "f"(lo));
    return r;
}
__device__ __forceinline__ uint32_t to_tf32(float f) {
    uint32_t r;
    asm("cvt.rna.tf32.f32 %0, %1;" : "=r"(r) : "f"(f));
    return r;
}
__device__ __forceinline__ void mma_bf16(float c[4], uint32_t a0, uint32_t a1, uint32_t a2, uint32_t a3,
                                         uint32_t b0, uint32_t b1) {
    asm volatile("mma.sync.aligned.m16n8k16.row.col.f32.bf16.bf16.f32 "
                 "{%0,%1,%2,%3}, {%4,%5,%6,%7}, {%8,%9}, {%0,%1,%2,%3};"
                 : "+f"(c[0]), "+f"(c[1]), "+f"(c[2]), "+f"(c[3])
                 : "r"(a0), "r"(a1), "r"(a2), "r"(a3), "r"(b0), "r"(b1));
}
__device__ __forceinline__ void mma_tf32(float c[4], uint32_t a0, uint32_t a1, uint32_t a2, uint32_t a3,
                                         uint32_t b0, uint32_t b1) {
    asm volatile("mma.sync.aligned.m16n8k8.row.col.f32.tf32.tf32.f32 "
                 "{%0,%1,%2,%3}, {%4,%5,%6,%7}, {%8,%9}, {%0,%1,%2,%3};"
                 : "+f"(c[0]), "+f"(c[1]), "+f"(c[2]), "+f"(c[3])
                 : "r"(a0), "r"(a1), "r"(a2), "r"(a3), "r"(b0), "r"(b1));
}
// leaky(0.25*s) then exp, folded into exp2: 0.25*log2e = 0.36067376, 0.05*log2e = 0.07213475
__device__ __forceinline__ float expleaky(float s, uint32_t bit) {
    float s2 = s > 0.f ? s * 0.36067376f : s * 0.07213475f;
    return bit ? exp2f(s2) : 0.f;
}

// ================= scratch =================
__device__ float g_combined[ROWS * Cc];
__device__ __nv_bfloat16 g_qb[Hh * ROWS * Kk];
__device__ __nv_bfloat16 g_kb[Hh * ROWS * Kk];
__device__ __nv_bfloat16 g_vtb[Hh * Bb * 128 * 1024];   // [h*8+b][c<128][m]
__device__ float g_v128[Hh * Bb * 1024];                // v col 128
__device__ uint32_t g_adjbits[Nn * 32];
__device__ float g_hp[ROWS * 4 * 132];                  // [row][h][132 padded], normalized
__device__ float g_hn[Mm * Dd];
__device__ float g_u[Mm * Dd];
__device__ float g_sel2[Mm * Cc];
__device__ uint32_t g_w1t[4 * 129 * 132];               // tf32, transposed [kc][n][u]
__device__ uint32_t g_w2t[129 * 132];

// ---------------- K0b: pack adjacency bits ----------------
__global__ void k_adjpack(const int* __restrict__ adj) {
    int idx = blockIdx.x * 256 + threadIdx.x;
    uint32_t bits = __ballot_sync(0xFFFFFFFFu, adj[idx] != 0);
    if ((idx & 31) == 0) g_adjbits[idx >> 5] = bits;
}

// ---------------- K0c: pre-transpose W1/W2 to tf32 ----------------
__global__ void k_wprep(const float* __restrict__ W1, const float* __restrict__ W2) {
    int idx = blockIdx.x * 256 + threadIdx.x;   // over 5*129*132
    if (idx >= 5 * 129 * 132) return;
    int m = idx / (129 * 132);
    int r = idx - m * (129 * 132);
    int n = r / 132, u = r - n * 132;
    uint32_t v = 0;
    if (u < 129)
        v = to_tf32(m < 4 ? W1[((size_t)m * 129 + u) * 129 + n]
                          : W2[(size_t)u * 129 + n]);
    if (m < 4) g_w1t[idx] = v;
    else       g_w2t[r] = v;
}

// ---------------- K1: fused concat + q/k/v projections via bf16 mma ----------------
#define QKV_AB_OFF 0
#define QKV_WT_OFF 19456
#define QKV_BS_OFF (19456 + 53504)
#define SMEM_QKV (QKV_BS_OFF + 176 * 4)

__global__ void __launch_bounds__(256, 2) k_qkv(const float* __restrict__ x, const float* __restrict__ h,
                                                const float* __restrict__ Wv, const float* __restrict__ bv,
                                                const float* __restrict__ Wq, const float* __restrict__ bq,
                                                const float* __restrict__ Wk, const float* __restrict__ bk) {
    extern __shared__ char smc[];
    uint32_t* Ab = (uint32_t*)(smc + QKV_AB_OFF);
    uint32_t* Wt = (uint32_t*)(smc + QKV_WT_OFF);
    float* bias_s = (float*)(smc + QKV_BS_OFF);
    int tile = blockIdx.x, hh = blockIdx.y, tid = threadIdx.x;
    int w = tid >> 5, lane = tid & 31, g = lane >> 2, t = lane & 3;
    int wm = w & 3, wn = w >> 2;
    int m0 = wm * 16;

    for (int e = tid; e < 64 * 76; e += 256) {
        int r = e / 76, u = e - r * 76;
        int row = tile * 64 + r;
        uint32_t val = 0;
        if (u < 65) {
            int c0 = 2 * u, c1 = 2 * u + 1;
            float f0 = (c0 < 65) ? x[row * 65 + c0] : h[row * 64 + (c0 - 65)];
            float f1 = 0.f;
            if (c1 < 129) f1 = (c1 < 65) ? x[row * 65 + c1] : h[row * 64 + (c1 - 65)];
            val = cvt_bf16x2(f1, f0);
            if (hh == 0) {
                g_combined[row * Cc + c0] = f0;
                if (c1 < 129) g_combined[row * Cc + c1] = f1;
            }
        }
        Ab[e] = val;
    }
    const float* wvh = Wv + (size_t)hh * 129 * 129;
    const float* wqh = Wq + (size_t)hh * 129 * 16;
    const float* wkh = Wk + (size_t)hh * 129 * 16;
    for (int e = tid; e < 76 * 176; e += 256) {
        int u = e / 176, n = e - u * 176;
        float w0 = 0.f, w1 = 0.f;
        if (u < 65) {
            int k0 = 2 * u, k1 = 2 * u + 1;
            if (n < 129) {
                w0 = wvh[k0 * 129 + n];
                if (k1 < 129) w1 = wvh[k1 * 129 + n];
            } else if (n >= 136 && n < 152) {
                int kk = n - 136;
                w0 = wqh[k0 * 16 + kk];
                if (k1 < 129) w1 = wqh[k1 * 16 + kk];
            } else if (n >= 152 && n < 168) {
                int kk = n - 152;
                w0 = wkh[k0 * 16 + kk];
                if (k1 < 129) w1 = wkh[k1 * 16 + kk];
            }
        }
        Wt[n * 76 + u] = cvt_bf16x2(w1, w0);
    }
    for (int e = tid; e < 176; e += 256) {
        float bval = 0.f;
        if (e < 129) bval = bv[hh * 129 + e];
        else if (e >= 136 && e < 152) bval = bq[hh * 16 + e - 136];
        else if (e >= 152 && e < 168) bval = bk[hh * 16 + e - 152];
        bias_s[e] = bval;
    }
    __syncthreads();

    float acc[11][4];
    #pragma unroll
    for (int i = 0; i < 11; i++) { acc[i][0] = acc[i][1] = acc[i][2] = acc[i][3] = 0.f; }
    int ntb = wn * 11;

    #pragma unroll
    for (int ks = 0; ks < 9; ks++) {
        uint32_t a0 = Ab[(m0 + g) * 76 + 8 * ks + t];
        uint32_t a1 = Ab[(m0 + g + 8) * 76 + 8 * ks + t];
        uint32_t a2 = Ab[(m0 + g) * 76 + 8 * ks + t + 4];
        uint32_t a3 = Ab[(m0 + g + 8) * 76 + 8 * ks + t + 4];
        #pragma unroll
        for (int i = 0; i < 11; i++) {
            int nt = ntb + i;
            uint32_t b0 = Wt[(8 * nt + g) * 76 + 8 * ks + t];
            uint32_t b1 = Wt[(8 * nt + g) * 76 + 8 * ks + t + 4];
            mma_bf16(acc[i], a0, a1, a2, a3, b0, b1);
        }
    }

    size_t rowbase = (size_t)hh * ROWS + tile * 64 + m0;
    if (wn == 1) {
        #pragma unroll
        for (int i = 6; i < 10; i++) {
            int nt = 11 + i;
            bool isq = nt < 19;
            int col = (nt - (isq ? 17 : 19)) * 8 + 2 * t;
            float b0v = bias_s[(isq ? 136 : 152) + col];
            float b1v = bias_s[(isq ? 136 : 152) + col + 1];
            __nv_bfloat16* dst = isq ? g_qb : g_kb;
            *(uint32_t*)&dst[(rowbase + g) * 16 + col] =
                cvt_bf16x2(acc[i][1] + b1v, acc[i][0] + b0v);
            *(uint32_t*)&dst[(rowbase + g + 8) * 16 + col] =
                cvt_bf16x2(acc[i][3] + b1v, acc[i][2] + b0v);
        }
    }
    __syncthreads();
    float* vtile = (float*)smc;
    #pragma unroll
    for (int i = 0; i < 11; i++) {
        int nt = ntb + i;
        if (nt > 16) break;
        int col = 8 * nt + 2 * t;
        if (col <= 128) {
            float bb = bias_s[col];
            vtile[(m0 + g) * 132 + col]     = acc[i][0] + bb;
            vtile[(m0 + g + 8) * 132 + col] = acc[i][2] + bb;
        }
        if (col + 1 <= 128) {
            float bb = bias_s[col + 1];
            vtile[(m0 + g) * 132 + col + 1]     = acc[i][1] + bb;
            vtile[(m0 + g + 8) * 132 + col + 1] = acc[i][3] + bb;
        }
    }
    __syncthreads();

    int b_idx = tile >> 4;
    int mbase = (tile & 15) * 64;
    size_t hb = hh * 8 + b_idx;
    for (int e = tid; e < 128 * 32; e += 256) {
        int c = e >> 5, mp = e & 31;
        float f0 = vtile[(mp * 2) * 132 + c];
        float f1 = vtile[(mp * 2 + 1) * 132 + c];
        *(__nv_bfloat162*)&g_vtb[(hb * 128 + c) * 1024 + mbase + mp * 2] =
            __float22bfloat162_rn(make_float2(f0, f1));
    }
    if (tid < 64)
        g_v128[hb * 1024 + mbase + tid] = vtile[tid * 132 + 128];
}

// ---------------- K3: HMMA flash attention, 64-row CTAs, 2 CTA/SM ----------------
#define AKS_OFF 0
#define AVT_OFF 6144
#define AV1_OFF (6144 + 34816)
#define SMEM_ATT (AV1_OFF + 512)

__global__ void __launch_bounds__(128, 2) k_attn_mma() {
    extern __shared__ char smc[];
    uint32_t* Ks  = (uint32_t*)(smc + AKS_OFF);
    uint32_t* VTs = (uint32_t*)(smc + AVT_OFF);
    float*    v1s = (float*)(smc + AV1_OFF);
    int tid = threadIdx.x, w = tid >> 5, lane = tid & 31;
    int g = lane >> 2, t = lane & 3;
    int rblk = blockIdx.x, b = blockIdx.y, hh = blockIdx.z;
    size_t hb = hh * 8 + b;
    int brow = b * 1024 + rblk * 64;

    const __nv_bfloat16* qsrc = g_qb + ((size_t)hh * ROWS + brow + 16 * w) * 16;
    uint32_t qa0 = *(const uint32_t*)(qsrc + g * 16 + 2 * t);
    uint32_t qa1 = *(const uint32_t*)(qsrc + (g + 8) * 16 + 2 * t);
    uint32_t qa2 = *(const uint32_t*)(qsrc + g * 16 + 2 * t + 8);
    uint32_t qa3 = *(const uint32_t*)(qsrc + (g + 8) * 16 + 2 * t + 8);

    int nrow0 = rblk * 64 + 16 * w + g;
    int nrow1 = nrow0 + 8;

    float O[16][4];
    #pragma unroll
    for (int i = 0; i < 16; i++) { O[i][0] = O[i][1] = O[i][2] = O[i][3] = 0.f; }
    float rs0 = 0.f, rs1 = 0.f, ax0 = 0.f, ax1 = 0.f;

    const uint32_t* kbase = (const uint32_t*)(g_kb + ((size_t)hh * ROWS + b * 1024) * 16);
    const __nv_bfloat16* vbase = g_vtb + hb * 131072;

    for (int j = 0; j < 8; j++) {
        __syncthreads();
        const uint32_t* ks = kbase + j * 128 * 8;
        #pragma unroll
        for (int it = 0; it < 8; it++) {
            int e = tid + 128 * it;
            int r = e >> 3, c8 = e & 7;
            Ks[r * 12 + c8] = ks[e];
        }
        #pragma unroll
        for (int it = 0; it < 16; it++) {
            int e = tid + 128 * it;
            int c = e >> 4, q = e & 15;
            ((uint4*)(smc + AVT_OFF + c * 272))[q] =
                ((const uint4*)(vbase + (size_t)c * 1024 + j * 128))[q];
        }
        v1s[tid] = g_v128[hb * 1024 + j * 128 + tid];
        uint4 A0 = ((const uint4*)g_adjbits)[nrow0 * 8 + j];
        uint4 A1 = ((const uint4*)g_adjbits)[nrow1 * 8 + j];
        __syncthreads();

        uint32_t af[8][4];
        #pragma unroll
        for (int nt = 0; nt < 16; nt++) {
            uint32_t b0 = Ks[(8 * nt + g) * 12 + t];
            uint32_t b1 = Ks[(8 * nt + g) * 12 + t + 4];
            float c[4] = {0.f, 0.f, 0.f, 0.f};
            mma_bf16(c, qa0, qa1, qa2, qa3, b0, b1);
            uint32_t wA = (nt < 4) ? A0.x : (nt < 8) ? A0.y : (nt < 12) ? A0.z : A0.w;
            uint32_t wB = (nt < 4) ? A1.x : (nt < 8) ? A1.y : (nt < 12) ? A1.z : A1.w;
            int bitb = ((nt & 3) << 3) + 2 * t;
            float p00 = expleaky(c[0], (wA >> bitb) & 1);
            float p01 = expleaky(c[1], (wA >> (bitb + 1)) & 1);
            float p10 = expleaky(c[2], (wB >> bitb) & 1);
            float p11 = expleaky(c[3], (wB >> (bitb + 1)) & 1);
            rs0 += p00 + p01; rs1 += p10 + p11;
            float2 v2 = *(const float2*)&v1s[8 * nt + 2 * t];
            ax0 += p00 * v2.x + p01 * v2.y;
            ax1 += p10 * v2.x + p11 * v2.y;
            int kc = nt >> 1;
            if ((nt & 1) == 0) {
                af[kc][0] = cvt_bf16x2(p01, p00);
                af[kc][1] = cvt_bf16x2(p11, p10);
            } else {
                af[kc][2] = cvt_bf16x2(p01, p00);
                af[kc][3] = cvt_bf16x2(p11, p10);
            }
        }
        #pragma unroll
        for (int kc = 0; kc < 8; kc++) {
            #pragma unroll
            for (int nt2 = 0; nt2 < 16; nt2++) {
                uint32_t b0 = VTs[(8 * nt2 + g) * 68 + 8 * kc + t];
                uint32_t b1 = VTs[(8 * nt2 + g) * 68 + 8 * kc + t + 4];
                mma_bf16(O[nt2], af[kc][0], af[kc][1], af[kc][2], af[kc][3], b0, b1);
            }
        }
    }

    rs0 += __shfl_xor_sync(0xFFFFFFFFu, rs0, 1); rs0 += __shfl_xor_sync(0xFFFFFFFFu, rs0, 2);
    rs1 += __shfl_xor_sync(0xFFFFFFFFu, rs1, 1); rs1 += __shfl_xor_sync(0xFFFFFFFFu, rs1, 2);
    ax0 += __shfl_xor_sync(0xFFFFFFFFu, ax0, 1); ax0 += __shfl_xor_sync(0xFFFFFFFFu, ax0, 2);
    ax1 += __shfl_xor_sync(0xFFFFFFFFu, ax1, 1); ax1 += __shfl_xor_sync(0xFFFFFFFFu, ax1, 2);
    float inv0 = 1.f / rs0, inv1 = 1.f / rs1;

    float* d0 = g_hp + ((size_t)(brow + 16 * w + g) * 4 + hh) * 132;
    float* d1 = d0 + 8 * 4 * 132;
    #pragma unroll
    for (int nt2 = 0; nt2 < 16; nt2++) {
        *(float2*)&d0[8 * nt2 + 2 * t] = make_float2(O[nt2][0] * inv0, O[nt2][1] * inv0);
        *(float2*)&d1[8 * nt2 + 2 * t] = make_float2(O[nt2][2] * inv1, O[nt2][3] * inv1);
    }
    if (t == 0) { d0[128] = ax0 * inv0; d1[128] = ax1 * inv1; }
}

// ---------------- K4: attention MLP + skip; pre-transposed tf32 W copy ----------------
#define MLP_A_OFF 0                         // u32[32*140] = 17920 (aliased as Hs after GEMM1)
#define MLP_W_OFF 17920                     // u32[136*140] = 76160
#define MLP_B_OFF (17920 + 76160)           // f32[272]
#define SMEM_MLP (MLP_B_OFF + 272 * 4)

__global__ void __launch_bounds__(256, 2) k_mlp(const float* __restrict__ b1, const float* __restrict__ b2) {
    extern __shared__ char smc[];
    uint32_t* As = (uint32_t*)(smc + MLP_A_OFF);
    uint32_t* Ws = (uint32_t*)(smc + MLP_W_OFF);
    float* bias_s = (float*)(smc + MLP_B_OFF);
    int blk = blockIdx.x, tid = threadIdx.x;
    int w = tid >> 5, lane = tid & 31, g = lane >> 2, t = lane & 3;
    int wm = w & 1, wn = w >> 1;
    int m0 = wm * 16;
    int NT = wn ? 4 : 5;
    int ntb = wn ? (4 * wn + 1) : 0;

    for (int e = tid; e < 272; e += 256) {
        float bval = 0.f;
        if (e < 129) bval = b1[e];
        else if (e >= 136 && e < 265) bval = b2[e - 136];
        bias_s[e] = bval;
    }
    // zero-pad As cols >=129 and Ws pad rows/cols once
    for (int e = tid; e < 32 * 140; e += 256) {
        int u = e - (e / 140) * 140;
        if (u >= 129) As[e] = 0;
    }
    for (int e = tid; e < 136 * 140; e += 256) {
        int n = e / 140, u = e - n * 140;
        if (n >= 129 || u >= 132) Ws[e] = 0;
    }

    float areg[17];
    auto ldA = [&](int kc) {
        #pragma unroll
        for (int it = 0; it < 17; it++) {
            int e = tid + 256 * it;
            if (e < 4128) {
                int r = e / 129, u = e - r * 129;
                areg[it] = g_hp[((size_t)(blk * 32 + r) * 4 + kc) * 132 + u];
            }
        }
    };
    auto stA = [&]() {
        #pragma unroll
        for (int it = 0; it < 17; it++) {
            int e = tid + 256 * it;
            if (e < 4128) {
                int r = e / 129, u = e - r * 129;
                As[r * 140 + u] = to_tf32(areg[it]);
            }
        }
    };
    // pure coalesced copy from pre-transposed tf32 W
    auto fillW = [&](const uint32_t* Wt) {
        for (int e = tid; e < 129 * 132; e += 256) {
            int n = e / 132, u = e - n * 132;
            Ws[n * 140 + u] = Wt[e];
        }
    };

    float acc[5][4];
    #pragma unroll
    for (int i = 0; i < 5; i++) { acc[i][0] = acc[i][1] = acc[i][2] = acc[i][3] = 0.f; }

    ldA(0);
    stA();
    fillW(g_w1t);
    __syncthreads();

    for (int kc = 0; kc < 4; kc++) {
        if (kc < 3) ldA(kc + 1);
        #pragma unroll
        for (int ks = 0; ks < 17; ks++) {
            uint32_t a0 = As[(m0 + g) * 140 + 8 * ks + t];
            uint32_t a1 = As[(m0 + g + 8) * 140 + 8 * ks + t];
            uint32_t a2 = As[(m0 + g) * 140 + 8 * ks + t + 4];
            uint32_t a3 = As[(m0 + g + 8) * 140 + 8 * ks + t + 4];
            #pragma unroll
            for (int i = 0; i < 5; i++) {
                if (i >= NT) break;
                int nt = ntb + i;
                uint32_t b0 = Ws[(8 * nt + g) * 140 + 8 * ks + t];
                uint32_t b1r = Ws[(8 * nt + g) * 140 + 8 * ks + t + 4];
                mma_tf32(acc[i], a0, a1, a2, a3, b0, b1r);
            }
        }
        __syncthreads();
        if (kc < 3) {
            stA();
            fillW(g_w1t + (kc + 1) * 129 * 132);
            __syncthreads();
        }
    }
    uint32_t* Hs = As;
    #pragma unroll
    for (int i = 0; i < 5; i++) {
        if (i >= NT) break;
        int nt = ntb + i;
        int col = 8 * nt + 2 * t;
        if (col <= 128) {
            Hs[(m0 + g) * 140 + col]     = to_tf32(fmaxf(acc[i][0] + bias_s[col], 0.f));
            Hs[(m0 + g + 8) * 140 + col] = to_tf32(fmaxf(acc[i][2] + bias_s[col], 0.f));
        }
        if (col + 1 <= 128) {
            Hs[(m0 + g) * 140 + col + 1]     = to_tf32(fmaxf(acc[i][1] + bias_s[col + 1], 0.f));
            Hs[(m0 + g + 8) * 140 + col + 1] = to_tf32(fmaxf(acc[i][3] + bias_s[col + 1], 0.f));
        }
        acc[i][0] = acc[i][1] = acc[i][2] = acc[i][3] = 0.f;
    }
    __syncthreads();
    fillW(g_w2t);
    __syncthreads();
    #pragma unroll
    for (int ks = 0; ks < 17; ks++) {
        uint32_t a0 = Hs[(m0 + g) * 140 + 8 * ks + t];
        uint32_t a1 = Hs[(m0 + g + 8) * 140 + 8 * ks + t];
        uint32_t a2 = Hs[(m0 + g) * 140 + 8 * ks + t + 4];
        uint32_t a3 = Hs[(m0 + g + 8) * 140 + 8 * ks + t + 4];
        #pragma unroll
        for (int i = 0; i < 5; i++) {
            if (i >= NT) break;
            int nt = ntb + i;
            uint32_t b0 = Ws[(8 * nt + g) * 140 + 8 * ks + t];
            uint32_t b1r = Ws[(8 * nt + g) * 140 + 8 * ks + t + 4];
            mma_tf32(acc[i], a0, a1, a2, a3, b0, b1r);
        }
    }
    #pragma unroll
    for (int i = 0; i < 5; i++) {
        if (i >= NT) break;
        int nt = ntb + i;
        int col = 8 * nt + 2 * t;
        if (col <= 128) {
            int idx = (blk * 32 + m0 + g) * Cc + col;
            g_combined[idx]          += acc[i][0] + bias_s[136 + col];
            g_combined[idx + 8 * Cc] += acc[i][2] + bias_s[136 + col];
        }
        if (col + 1 <= 128) {
            int idx = (blk * 32 + m0 + g) * Cc + col + 1;
            g_combined[idx]          += acc[i][1] + bias_s[137 + col];
            g_combined[idx + 8 * Cc] += acc[i][3] + bias_s[137 + col];
        }
    }
}

// ---------------- K5: r,u gates; on-the-fly A, double-buffered W, 1 sync/iter ----------------
__global__ void __launch_bounds__(256, 2) k_gate_ru(const float* __restrict__ qv,
                                                    const int* __restrict__ nodes_b, const int* __restrict__ nodes_n,
                                                    const float* __restrict__ Wr, const float* __restrict__ br,
                                                    const float* __restrict__ Wu, const float* __restrict__ bu,
                                                    const float* __restrict__ x, const float* __restrict__ hin) {
    extern __shared__ float sm[];
    float*    sel_s = sm;                              // [32][132]
    float*    qv_s  = sel_s + 32 * 132;                // [32][33]
    uint32_t* Ws    = (uint32_t*)(qv_s + 32 * 33);     // [2 buf][2 mat][129][36]
    float*    bs    = (float*)(Ws + 2 * 2 * 129 * 36); // [2][32][34]
    int blk = blockIdx.x, nh = blockIdx.y, tid = threadIdx.x;
    int ob = nh * 32;
    int w = tid >> 5, lane = tid & 31;
    int g = lane >> 2, t = lane & 3;
    int mt = w & 1, mat = (w >> 1) & 1, nsub = w >> 2;
    int m0 = mt * 16, n0l = nsub * 16;

    for (int e = tid; e < 32 * 132; e += 256) {
        int lm = e / 132, i = e - lm * 132;
        int gm = blk * 32 + lm;
        int node = nodes_b[gm] * Nn + nodes_n[gm];
        sel_s[e] = (i < Cc) ? g_combined[node * Cc + i] : 0.f;
    }
    for (int e = tid; e < 32 * 32; e += 256) {
        int lm = e >> 5, d = e & 31;
        qv_s[lm * 33 + d] = qv[(blk * 32 + lm) * 32 + d];
    }
    for (int e = tid; e < 2048; e += 256) {
        int m2 = e >> 10, r2 = e & 1023;
        int d2 = r2 >> 5, o = r2 & 31;
        bs[m2 * 1088 + d2 * 34 + o] = (m2 ? bu : br)[d2 * 64 + ob + o];
    }

    float wreg[33];
    auto ldW = [&](int d) {
        #pragma unroll
        for (int it = 0; it < 33; it++) {
            int e = tid + 256 * it;
            if (e < 8256) {
                int m2 = (e >= 4128);
                int e2 = e - m2 * 4128;
                int k = e2 >> 5, o = e2 & 31;
                wreg[it] = (m2 ? Wu : Wr)[((size_t)d * Cc + k) * 64 + ob + o];
            }
        }
    };
    auto stW = [&](int buf) {
        #pragma unroll
        for (int it = 0; it < 33; it++) {
            int e = tid + 256 * it;
            if (e < 8256) {
                int m2 = (e >= 4128);
                int e2 = e - m2 * 4128;
                int k = e2 >> 5, o = e2 & 31;
                Ws[buf * 9288 + m2 * 4644 + k * 36 + o] = to_tf32(wreg[it]);
            }
        }
    };

    ldW(0);
    stW(0);
    __syncthreads();

    float acc[2][4] = {};
    const int selr0 = (m0 + g) * 132, selr1 = (m0 + g + 8) * 132;
    const int qvr0 = (m0 + g) * 33,  qvr1 = (m0 + g + 8) * 33;

    for (int d = 0; d < 32; d++) {
        if (d < 31) ldW(d + 1);
        float q0 = qv_s[qvr0 + d];
        float q1 = qv_s[qvr1 + d];
        const uint32_t* Wm = Ws + (d & 1) * 9288 + mat * 4644;
        #pragma unroll 4
        for (int ks = 0; ks < 16; ks++) {
            int k0 = ks * 8;
            uint32_t a0 = to_tf32(q0 * sel_s[selr0 + k0 + t]);
            uint32_t a1 = to_tf32(q1 * sel_s[selr1 + k0 + t]);
            uint32_t a2 = to_tf32(q0 * sel_s[selr0 + k0 + t + 4]);
            uint32_t a3 = to_tf32(q1 * sel_s[selr1 + k0 + t + 4]);
            #pragma unroll
            for (int cn = 0; cn < 2; cn++) {
                uint32_t b0 = Wm[(k0 + t) * 36 + n0l + cn * 8 + g];
                uint32_t b1 = Wm[(k0 + t + 4) * 36 + n0l + cn * 8 + g];
                mma_tf32(acc[cn], a0, a1, a2, a3, b0, b1);
            }
        }
        float z0 = q0 * sel_s[selr0 + 128];
        float z1 = q1 * sel_s[selr1 + 128];
        #pragma unroll
        for (int cn = 0; cn < 2; cn++) {
            float w0 = __uint_as_float(Wm[128 * 36 + n0l + cn * 8 + 2 * t]);
            float w1 = __uint_as_float(Wm[128 * 36 + n0l + cn * 8 + 2 * t + 1]);
            acc[cn][0] += z0 * w0; acc[cn][1] += z0 * w1;
            acc[cn][2] += z1 * w0; acc[cn][3] += z1 * w1;
        }
        if (d < 31) stW((d + 1) & 1);
        __syncthreads();
    }

    const float* bm = bs + mat * 1088;
    #pragma unroll 4
    for (int d = 0; d < 32; d++) {
        float q0 = qv_s[qvr0 + d];
        float q1 = qv_s[qvr1 + d];
        #pragma unroll
        for (int cn = 0; cn < 2; cn++) {
            float w0 = bm[d * 34 + n0l + cn * 8 + 2 * t];
            float w1 = bm[d * 34 + n0l + cn * 8 + 2 * t + 1];
            acc[cn][0] += q0 * w0; acc[cn][1] += q0 * w1;
            acc[cn][2] += q1 * w0; acc[cn][3] += q1 * w1;
        }
    }

    __syncthreads();
    float* stg = sel_s;
    int cb = mat * 40;
    #pragma unroll
    for (int cn = 0; cn < 2; cn++) {
        int col = cb + n0l + cn * 8 + 2 * t;
        stg[(m0 + g) * 132 + col]     = acc[cn][0];
        stg[(m0 + g) * 132 + col + 1] = acc[cn][1];
        stg[(m0 + g + 8) * 132 + col]     = acc[cn][2];
        stg[(m0 + g + 8) * 132 + col + 1] = acc[cn][3];
    }
    __syncthreads();

    for (int e = tid; e < 32 * 32; e += 256) {
        int lm = e >> 5, o = e & 31;
        int gm = blk * 32 + lm;
        int node = nodes_b[gm] * Nn + nodes_n[gm];
        float ar = stg[lm * 132 + o];
        float au = stg[lm * 132 + 40 + o];
        float hv = hin[node * 64 + ob + o];
        float r = 1.f / (1.f + __expf(-ar));
        float u = 1.f / (1.f + __expf(-au));
        float hn = r * hv;
        g_hn[gm * 64 + ob + o] = hn;
        g_u[gm * 64 + ob + o] = u;
        g_sel2[gm * Cc + 65 + ob + o] = hn;
    }
    if (nh == 0) {
        for (int e = tid; e < 32 * 65; e += 256) {
            int lm = e / 65, i = e - lm * 65;
            int gm = blk * 32 + lm;
            int node = nodes_b[gm] * Nn + nodes_n[gm];
            g_sel2[gm * Cc + i] = x[node * 65 + i];
        }
    }
}

// ---------------- K6: cand gate; on-the-fly A, double-buffered W, 1 sync/iter ----------------
__global__ void __launch_bounds__(128, 3) k_gate_c(const float* __restrict__ qv,
                                                   const float* __restrict__ Wc, const float* __restrict__ bc,
                                                   float* __restrict__ out) {
    extern __shared__ float sm[];
    float*    sel_s = sm;                              // [32][132]
    float*    qv_s  = sel_s + 32 * 132;                // [32][33]
    uint32_t* Ws    = (uint32_t*)(qv_s + 32 * 33);     // [2 buf][129][36]
    float*    bs    = (float*)(Ws + 2 * 129 * 36);     // [32][34]
    int blk = blockIdx.x, nh = blockIdx.y, tid = threadIdx.x;
    int ob = nh * 32;
    int w = tid >> 5, lane = tid & 31;
    int g = lane >> 2, t = lane & 3;
    int mt = w & 1, nsub = w >> 1;
    int m0 = mt * 16, n0l = nsub * 16;

    for (int e = tid; e < 32 * 132; e += 128) {
        int lm = e / 132, i = e - lm * 132;
        sel_s[e] = (i < Cc) ? g_sel2[(blk * 32 + lm) * Cc + i] : 0.f;
    }
    for (int e = tid; e < 32 * 32; e += 128) {
        int lm = e >> 5, d = e & 31;
        qv_s[lm * 33 + d] = qv[(blk * 32 + lm) * 32 + d];
    }
    for (int e = tid; e < 1024; e += 128) {
        int d2 = e >> 5, o = e & 31;
        bs[d2 * 34 + o] = bc[d2 * 64 + ob + o];
    }

    float wreg[33];
    auto ldW = [&](int d) {
        #pragma unroll
        for (int it = 0; it < 33; it++) {
            int e = tid + 128 * it;
            if (e < 4128) {
                int k = e >> 5, o = e & 31;
                wreg[it] = Wc[((size_t)d * Cc + k) * 64 + ob + o];
            }
        }
    };
    auto stW = [&](int buf) {
        #pragma unroll
        for (int it = 0; it < 33; it++) {
            int e = tid + 128 * it;
            if (e < 4128) {
                int k = e >> 5, o = e & 31;
                Ws[buf * 4644 + k * 36 + o] = to_tf32(wreg[it]);
            }
        }
    };

    ldW(0);
    stW(0);
    __syncthreads();

    float acc[2][4] = {};
    const int selr0 = (m0 + g) * 132, selr1 = (m0 + g + 8) * 132;
    const int qvr0 = (m0 + g) * 33,  qvr1 = (m0 + g + 8) * 33;

    for (int d = 0; d < 32; d++) {
        if (d < 31) ldW(d + 1);
        float q0 = qv_s[qvr0 + d];
        float q1 = qv_s[qvr1 + d];
        const uint32_t* Wm = Ws + (d & 1) * 4644;
        #pragma unroll 4
        for (int ks = 0; ks < 16; ks++) {
            int k0 = ks * 8;
            uint32_t a0 = to_tf32(q0 * sel_s[selr0 + k0 + t]);
            uint32_t a1 = to_tf32(q1 * sel_s[selr1 + k0 + t]);
            uint32_t a2 = to_tf32(q0 * sel_s[selr0 + k0 + t + 4]);
            uint32_t a3 = to_tf32(q1 * sel_s[selr1 + k0 + t + 4]);
            #pragma unroll
            for (int cn = 0; cn < 2; cn++) {
                uint32_t b0 = Wm[(k0 + t) * 36 + n0l + cn * 8 + g];
                uint32_t b1 = Wm[(k0 + t + 4) * 36 + n0l + cn * 8 + g];
                mma_tf32(acc[cn], a0, a1, a2, a3, b0, b1);
            }
        }
        float z0 = q0 * sel_s[selr0 + 128];
        float z1 = q1 * sel_s[selr1 + 128];
        #pragma unroll
        for (int cn = 0; cn < 2; cn++) {
            float w0 = __uint_as_float(Wm[128 * 36 + n0l + cn * 8 + 2 * t]);
            float w1 = __uint_as_float(Wm[128 * 36 + n0l + cn * 8 + 2 * t + 1]);
            acc[cn][0] += z0 * w0; acc[cn][1] += z0 * w1;
            acc[cn][2] += z1 * w0; acc[cn][3] += z1 * w1;
        }
        if (d < 31) stW((d + 1) & 1);
        __syncthreads();
    }

    #pragma unroll 4
    for (int d = 0; d < 32; d++) {
        float q0 = qv_s[qvr0 + d];
        float q1 = qv_s[qvr1 + d];
        #pragma unroll
        for (int cn = 0; cn < 2; cn++) {
            float w0 = bs[d * 34 + n0l + cn * 8 + 2 * t];
            float w1 = bs[d * 34 + n0l + cn * 8 + 2 * t + 1];
            acc[cn][0] += q0 * w0; acc[cn][1] += q0 * w1;
            acc[cn][2] += q1 * w0; acc[cn][3] += q1 * w1;
        }
    }

    int gm0 = blk * 32 + m0 + g;
    int gm1 = gm0 + 8;
    #pragma unroll
    for (int cn = 0; cn < 2; cn++) {
        int col = ob + n0l + cn * 8 + 2 * t;
        #pragma unroll
        for (int jj = 0; jj < 2; jj++) {
            int gm = jj ? gm1 : gm0;
            float c0 = acc[cn][2 * jj], c1 = acc[cn][2 * jj + 1];
            float u0 = g_u[gm * 64 + col],     hn0 = g_hn[gm * 64 + col];
            float u1 = g_u[gm * 64 + col + 1], hn1 = g_hn[gm * 64 + col + 1];
            out[gm * 64 + col]     = (1.f - u0) * hn0 + u0 * tanhf(c0);
            out[gm * 64 + col + 1] = (1.f - u1) * hn1 + u1 * tanhf(c1);
        }
    }
}

// ---------------- launch ----------------
extern "C" void kernel_launch(void* const* d_in, const int* in_sizes, int n_in,
                              void* d_out, int out_size) {
    const float* x   = (const float*)d_in[0];
    const float* h   = (const float*)d_in[1];
    const float* qv  = (const float*)d_in[2];
    const int*   adj = (const int*)  d_in[3];
    const int*   nb  = (const int*)  d_in[4];
    const int*   nn  = (const int*)  d_in[5];
    const float* Wq  = (const float*)d_in[6];
    const float* bq  = (const float*)d_in[7];
    const float* Wk  = (const float*)d_in[8];
    const float* bk  = (const float*)d_in[9];
    const float* Wv  = (const float*)d_in[10];
    const float* bv  = (const float*)d_in[11];
    const float* W1  = (const float*)d_in[12];
    const float* b1  = (const float*)d_in[13];
    const float* W2  = (const float*)d_in[14];
    const float* b2  = (const float*)d_in[15];
    const float* Wr  = (const float*)d_in[16];
    const float* br  = (const float*)d_in[17];
    const float* Wu  = (const float*)d_in[18];
    const float* bu  = (const float*)d_in[19];
    const float* Wc  = (const float*)d_in[20];
    const float* bc  = (const float*)d_in[21];
    float* out = (float*)d_out;

    const int SZ_RU = (32 * 132 + 32 * 33 + 2 * 2 * 129 * 36 + 2 * 32 * 34 + 16) * 4;
    const int SZ_C  = (32 * 132 + 32 * 33 + 2 * 129 * 36 + 32 * 34 + 16) * 4;

    cudaFuncSetAttribute(k_qkv,      cudaFuncAttributeMaxDynamicSharedMemorySize, SMEM_QKV);
    cudaFuncSetAttribute(k_attn_mma, cudaFuncAttributeMaxDynamicSharedMemorySize, SMEM_ATT);
    cudaFuncSetAttribute(k_mlp,      cudaFuncAttributeMaxDynamicSharedMemorySize, SMEM_MLP);
    cudaFuncSetAttribute(k_gate_ru,  cudaFuncAttributeMaxDynamicSharedMemorySize, SZ_RU);
    cudaFuncSetAttribute(k_gate_c,   cudaFuncAttributeMaxDynamicSharedMemorySize, SZ_C);

    k_adjpack<<<(Nn * Nn) / 256, 256>>>(adj);
    k_wprep<<<(5 * 129 * 132 + 255) / 256, 256>>>(W1, W2);
    k_qkv<<<dim3(128, 4), 256, SMEM_QKV>>>(x, h, Wv, bv, Wq, bq, Wk, bk);
    k_attn_mma<<<dim3(16, 8, 4), 128, SMEM_ATT>>>();
    k_mlp<<<256, 256, SMEM_MLP>>>(b1, b2);
    k_gate_ru<<<dim3(128, 2), 256, SZ_RU>>>(qv, nb, nn, Wr, br, Wu, bu, x, h);
    k_gate_c<<<dim3(128, 2), 128, SZ_C>>>(qv, Wc, bc, out);
}

// round 16
// speedup vs baseline: 1.1275x; 1.1275x over previous
#include <cuda_runtime.h>
#include <cuda_bf16.h>
#include <cstdint>
#include <math.h>

#define Bb   8
#define Nn   1024
#define Dd   64
#define Hh   4
#define Cc   129
#define Kk   16
#define Mm   4096
#define ROWS 8192   // B*N

// ---------------- helpers ----------------
__device__ __forceinline__ uint32_t cvt_bf16x2(float hi, float lo) {
    uint32_t r;
    asm("cvt.rn.bf16x2.f32 %0, %1, %2;" : "=r"(r) : "f"(hi), "f"(lo));
    return r;
}
__device__ __forceinline__ uint32_t to_tf32(float f) {
    uint32_t r;
    asm("cvt.rna.tf32.f32 %0, %1;" : "=r"(r) : "f"(f));
    return r;
}
__device__ __forceinline__ void mma_bf16(float c[4], uint32_t a0, uint32_t a1, uint32_t a2, uint32_t a3,
                                         uint32_t b0, uint32_t b1) {
    asm volatile("mma.sync.aligned.m16n8k16.row.col.f32.bf16.bf16.f32 "
                 "{%0,%1,%2,%3}, {%4,%5,%6,%7}, {%8,%9}, {%0,%1,%2,%3};"
                 : "+f"(c[0]), "+f"(c[1]), "+f"(c[2]), "+f"(c[3])
                 : "r"(a0), "r"(a1), "r"(a2), "r"(a3), "r"(b0), "r"(b1));
}
__device__ __forceinline__ void mma_tf32(float c[4], uint32_t a0, uint32_t a1, uint32_t a2, uint32_t a3,
                                         uint32_t b0, uint32_t b1) {
    asm volatile("mma.sync.aligned.m16n8k8.row.col.f32.tf32.tf32.f32 "
                 "{%0,%1,%2,%3}, {%4,%5,%6,%7}, {%8,%9}, {%0,%1,%2,%3};"
                 : "+f"(c[0]), "+f"(c[1]), "+f"(c[2]), "+f"(c[3])
                 : "r"(a0), "r"(a1), "r"(a2), "r"(a3), "r"(b0), "r"(b1));
}
__device__ __forceinline__ float ex2_approx(float x) {
    float r;
    asm("ex2.approx.ftz.f32 %0, %1;" : "=f"(r) : "f"(x));
    return r;
}
// leaky(0.25*s) then exp, folded: 0.25*log2e = 0.36067376, 0.05*log2e = 0.07213475
__device__ __forceinline__ float expleaky(float s, uint32_t bit) {
    float s2 = s > 0.f ? s * 0.36067376f : s * 0.07213475f;
    return bit ? ex2_approx(s2) : 0.f;
}

// ================= scratch =================
__device__ float g_combined[ROWS * Cc];
__device__ __nv_bfloat16 g_qb[Hh * ROWS * Kk];
__device__ __nv_bfloat16 g_kb[Hh * ROWS * Kk];
__device__ __nv_bfloat16 g_vtb[Hh * Bb * 128 * 1024];   // [h*8+b][c<128][m]
__device__ float g_v128[Hh * Bb * 1024];                // v col 128
__device__ uint32_t g_adjbits[Nn * 32];
__device__ float g_hp[ROWS * 4 * 132];                  // [row][h][132 padded], normalized
__device__ float g_hn[Mm * Dd];
__device__ float g_u[Mm * Dd];
__device__ float g_sel2[Mm * Cc];
__device__ uint32_t g_w1t[4 * 129 * 132];               // tf32, transposed [kc][n][u]
__device__ uint32_t g_w2t[129 * 132];

// ---------------- K0b: pack adjacency bits ----------------
__global__ void k_adjpack(const int* __restrict__ adj) {
    int idx = blockIdx.x * 256 + threadIdx.x;
    uint32_t bits = __ballot_sync(0xFFFFFFFFu, adj[idx] != 0);
    if ((idx & 31) == 0) g_adjbits[idx >> 5] = bits;
}

// ---------------- K0c: pre-transpose W1/W2 to tf32 ----------------
__global__ void k_wprep(const float* __restrict__ W1, const float* __restrict__ W2) {
    int idx = blockIdx.x * 256 + threadIdx.x;   // over 5*129*132
    if (idx >= 5 * 129 * 132) return;
    int m = idx / (129 * 132);
    int r = idx - m * (129 * 132);
    int n = r / 132, u = r - n * 132;
    uint32_t v = 0;
    if (u < 129)
        v = to_tf32(m < 4 ? W1[((size_t)m * 129 + u) * 129 + n]
                          : W2[(size_t)u * 129 + n]);
    if (m < 4) g_w1t[idx] = v;
    else       g_w2t[r] = v;
}

// ---------------- K1: fused concat + q/k/v projections via bf16 mma ----------------
#define QKV_AB_OFF 0
#define QKV_WT_OFF 19456
#define QKV_BS_OFF (19456 + 53504)
#define SMEM_QKV (QKV_BS_OFF + 176 * 4)

__global__ void __launch_bounds__(256, 2) k_qkv(const float* __restrict__ x, const float* __restrict__ h,
                                                const float* __restrict__ Wv, const float* __restrict__ bv,
                                                const float* __restrict__ Wq, const float* __restrict__ bq,
                                                const float* __restrict__ Wk, const float* __restrict__ bk) {
    extern __shared__ char smc[];
    uint32_t* Ab = (uint32_t*)(smc + QKV_AB_OFF);
    uint32_t* Wt = (uint32_t*)(smc + QKV_WT_OFF);
    float* bias_s = (float*)(smc + QKV_BS_OFF);
    int tile = blockIdx.x, hh = blockIdx.y, tid = threadIdx.x;
    int w = tid >> 5, lane = tid & 31, g = lane >> 2, t = lane & 3;
    int wm = w & 3, wn = w >> 2;
    int m0 = wm * 16;

    for (int e = tid; e < 64 * 76; e += 256) {
        int r = e / 76, u = e - r * 76;
        int row = tile * 64 + r;
        uint32_t val = 0;
        if (u < 65) {
            int c0 = 2 * u, c1 = 2 * u + 1;
            float f0 = (c0 < 65) ? x[row * 65 + c0] : h[row * 64 + (c0 - 65)];
            float f1 = 0.f;
            if (c1 < 129) f1 = (c1 < 65) ? x[row * 65 + c1] : h[row * 64 + (c1 - 65)];
            val = cvt_bf16x2(f1, f0);
            if (hh == 0) {
                g_combined[row * Cc + c0] = f0;
                if (c1 < 129) g_combined[row * Cc + c1] = f1;
            }
        }
        Ab[e] = val;
    }
    const float* wvh = Wv + (size_t)hh * 129 * 129;
    const float* wqh = Wq + (size_t)hh * 129 * 16;
    const float* wkh = Wk + (size_t)hh * 129 * 16;
    for (int e = tid; e < 76 * 176; e += 256) {
        int u = e / 176, n = e - u * 176;
        float w0 = 0.f, w1 = 0.f;
        if (u < 65) {
            int k0 = 2 * u, k1 = 2 * u + 1;
            if (n < 129) {
                w0 = wvh[k0 * 129 + n];
                if (k1 < 129) w1 = wvh[k1 * 129 + n];
            } else if (n >= 136 && n < 152) {
                int kk = n - 136;
                w0 = wqh[k0 * 16 + kk];
                if (k1 < 129) w1 = wqh[k1 * 16 + kk];
            } else if (n >= 152 && n < 168) {
                int kk = n - 152;
                w0 = wkh[k0 * 16 + kk];
                if (k1 < 129) w1 = wkh[k1 * 16 + kk];
            }
        }
        Wt[n * 76 + u] = cvt_bf16x2(w1, w0);
    }
    for (int e = tid; e < 176; e += 256) {
        float bval = 0.f;
        if (e < 129) bval = bv[hh * 129 + e];
        else if (e >= 136 && e < 152) bval = bq[hh * 16 + e - 136];
        else if (e >= 152 && e < 168) bval = bk[hh * 16 + e - 152];
        bias_s[e] = bval;
    }
    __syncthreads();

    float acc[11][4];
    #pragma unroll
    for (int i = 0; i < 11; i++) { acc[i][0] = acc[i][1] = acc[i][2] = acc[i][3] = 0.f; }
    int ntb = wn * 11;

    #pragma unroll
    for (int ks = 0; ks < 9; ks++) {
        uint32_t a0 = Ab[(m0 + g) * 76 + 8 * ks + t];
        uint32_t a1 = Ab[(m0 + g + 8) * 76 + 8 * ks + t];
        uint32_t a2 = Ab[(m0 + g) * 76 + 8 * ks + t + 4];
        uint32_t a3 = Ab[(m0 + g + 8) * 76 + 8 * ks + t + 4];
        #pragma unroll
        for (int i = 0; i < 11; i++) {
            int nt = ntb + i;
            uint32_t b0 = Wt[(8 * nt + g) * 76 + 8 * ks + t];
            uint32_t b1 = Wt[(8 * nt + g) * 76 + 8 * ks + t + 4];
            mma_bf16(acc[i], a0, a1, a2, a3, b0, b1);
        }
    }

    size_t rowbase = (size_t)hh * ROWS + tile * 64 + m0;
    if (wn == 1) {
        #pragma unroll
        for (int i = 6; i < 10; i++) {
            int nt = 11 + i;
            bool isq = nt < 19;
            int col = (nt - (isq ? 17 : 19)) * 8 + 2 * t;
            float b0v = bias_s[(isq ? 136 : 152) + col];
            float b1v = bias_s[(isq ? 136 : 152) + col + 1];
            __nv_bfloat16* dst = isq ? g_qb : g_kb;
            *(uint32_t*)&dst[(rowbase + g) * 16 + col] =
                cvt_bf16x2(acc[i][1] + b1v, acc[i][0] + b0v);
            *(uint32_t*)&dst[(rowbase + g + 8) * 16 + col] =
                cvt_bf16x2(acc[i][3] + b1v, acc[i][2] + b0v);
        }
    }
    __syncthreads();
    float* vtile = (float*)smc;
    #pragma unroll
    for (int i = 0; i < 11; i++) {
        int nt = ntb + i;
        if (nt > 16) break;
        int col = 8 * nt + 2 * t;
        if (col <= 128) {
            float bb = bias_s[col];
            vtile[(m0 + g) * 132 + col]     = acc[i][0] + bb;
            vtile[(m0 + g + 8) * 132 + col] = acc[i][2] + bb;
        }
        if (col + 1 <= 128) {
            float bb = bias_s[col + 1];
            vtile[(m0 + g) * 132 + col + 1]     = acc[i][1] + bb;
            vtile[(m0 + g + 8) * 132 + col + 1] = acc[i][3] + bb;
        }
    }
    __syncthreads();

    int b_idx = tile >> 4;
    int mbase = (tile & 15) * 64;
    size_t hb = hh * 8 + b_idx;
    for (int e = tid; e < 128 * 32; e += 256) {
        int c = e >> 5, mp = e & 31;
        float f0 = vtile[(mp * 2) * 132 + c];
        float f1 = vtile[(mp * 2 + 1) * 132 + c];
        *(__nv_bfloat162*)&g_vtb[(hb * 128 + c) * 1024 + mbase + mp * 2] =
            __float22bfloat162_rn(make_float2(f0, f1));
    }
    if (tid < 64)
        g_v128[hb * 1024 + mbase + tid] = vtile[tid * 132 + 128];
}

// ---------------- K3: HMMA flash attention, 64-row CTAs, 2 CTA/SM ----------------
#define AKS_OFF 0
#define AVT_OFF 6144
#define AV1_OFF (6144 + 34816)
#define SMEM_ATT (AV1_OFF + 512)

__global__ void __launch_bounds__(128, 2) k_attn_mma() {
    extern __shared__ char smc[];
    uint32_t* Ks  = (uint32_t*)(smc + AKS_OFF);
    uint32_t* VTs = (uint32_t*)(smc + AVT_OFF);
    float*    v1s = (float*)(smc + AV1_OFF);
    int tid = threadIdx.x, w = tid >> 5, lane = tid & 31;
    int g = lane >> 2, t = lane & 3;
    int rblk = blockIdx.x, b = blockIdx.y, hh = blockIdx.z;
    size_t hb = hh * 8 + b;
    int brow = b * 1024 + rblk * 64;

    const __nv_bfloat16* qsrc = g_qb + ((size_t)hh * ROWS + brow + 16 * w) * 16;
    uint32_t qa0 = *(const uint32_t*)(qsrc + g * 16 + 2 * t);
    uint32_t qa1 = *(const uint32_t*)(qsrc + (g + 8) * 16 + 2 * t);
    uint32_t qa2 = *(const uint32_t*)(qsrc + g * 16 + 2 * t + 8);
    uint32_t qa3 = *(const uint32_t*)(qsrc + (g + 8) * 16 + 2 * t + 8);

    int nrow0 = rblk * 64 + 16 * w + g;
    int nrow1 = nrow0 + 8;

    float O[16][4];
    #pragma unroll
    for (int i = 0; i < 16; i++) { O[i][0] = O[i][1] = O[i][2] = O[i][3] = 0.f; }
    float rs0 = 0.f, rs1 = 0.f, ax0 = 0.f, ax1 = 0.f;

    const uint32_t* kbase = (const uint32_t*)(g_kb + ((size_t)hh * ROWS + b * 1024) * 16);
    const __nv_bfloat16* vbase = g_vtb + hb * 131072;

    for (int j = 0; j < 8; j++) {
        __syncthreads();
        const uint32_t* ks = kbase + j * 128 * 8;
        #pragma unroll
        for (int it = 0; it < 8; it++) {
            int e = tid + 128 * it;
            int r = e >> 3, c8 = e & 7;
            Ks[r * 12 + c8] = ks[e];
        }
        #pragma unroll
        for (int it = 0; it < 16; it++) {
            int e = tid + 128 * it;
            int c = e >> 4, q = e & 15;
            ((uint4*)(smc + AVT_OFF + c * 272))[q] =
                ((const uint4*)(vbase + (size_t)c * 1024 + j * 128))[q];
        }
        v1s[tid] = g_v128[hb * 1024 + j * 128 + tid];
        uint4 A0 = ((const uint4*)g_adjbits)[nrow0 * 8 + j];
        uint4 A1 = ((const uint4*)g_adjbits)[nrow1 * 8 + j];
        __syncthreads();

        uint32_t af[8][4];
        #pragma unroll
        for (int nt = 0; nt < 16; nt++) {
            uint32_t b0 = Ks[(8 * nt + g) * 12 + t];
            uint32_t b1 = Ks[(8 * nt + g) * 12 + t + 4];
            float c[4] = {0.f, 0.f, 0.f, 0.f};
            mma_bf16(c, qa0, qa1, qa2, qa3, b0, b1);
            uint32_t wA = (nt < 4) ? A0.x : (nt < 8) ? A0.y : (nt < 12) ? A0.z : A0.w;
            uint32_t wB = (nt < 4) ? A1.x : (nt < 8) ? A1.y : (nt < 12) ? A1.z : A1.w;
            int bitb = ((nt & 3) << 3) + 2 * t;
            float p00 = expleaky(c[0], (wA >> bitb) & 1);
            float p01 = expleaky(c[1], (wA >> (bitb + 1)) & 1);
            float p10 = expleaky(c[2], (wB >> bitb) & 1);
            float p11 = expleaky(c[3], (wB >> (bitb + 1)) & 1);
            rs0 += p00 + p01; rs1 += p10 + p11;
            float2 v2 = *(const float2*)&v1s[8 * nt + 2 * t];
            ax0 += p00 * v2.x + p01 * v2.y;
            ax1 += p10 * v2.x + p11 * v2.y;
            int kc = nt >> 1;
            if ((nt & 1) == 0) {
                af[kc][0] = cvt_bf16x2(p01, p00);
                af[kc][1] = cvt_bf16x2(p11, p10);
            } else {
                af[kc][2] = cvt_bf16x2(p01, p00);
                af[kc][3] = cvt_bf16x2(p11, p10);
            }
        }
        #pragma unroll
        for (int kc = 0; kc < 8; kc++) {
            #pragma unroll
            for (int nt2 = 0; nt2 < 16; nt2++) {
                uint32_t b0 = VTs[(8 * nt2 + g) * 68 + 8 * kc + t];
                uint32_t b1 = VTs[(8 * nt2 + g) * 68 + 8 * kc + t + 4];
                mma_bf16(O[nt2], af[kc][0], af[kc][1], af[kc][2], af[kc][3], b0, b1);
            }
        }
    }

    rs0 += __shfl_xor_sync(0xFFFFFFFFu, rs0, 1); rs0 += __shfl_xor_sync(0xFFFFFFFFu, rs0, 2);
    rs1 += __shfl_xor_sync(0xFFFFFFFFu, rs1, 1); rs1 += __shfl_xor_sync(0xFFFFFFFFu, rs1, 2);
    ax0 += __shfl_xor_sync(0xFFFFFFFFu, ax0, 1); ax0 += __shfl_xor_sync(0xFFFFFFFFu, ax0, 2);
    ax1 += __shfl_xor_sync(0xFFFFFFFFu, ax1, 1); ax1 += __shfl_xor_sync(0xFFFFFFFFu, ax1, 2);
    float inv0 = 1.f / rs0, inv1 = 1.f / rs1;

    float* d0 = g_hp + ((size_t)(brow + 16 * w + g) * 4 + hh) * 132;
    float* d1 = d0 + 8 * 4 * 132;
    #pragma unroll
    for (int nt2 = 0; nt2 < 16; nt2++) {
        *(float2*)&d0[8 * nt2 + 2 * t] = make_float2(O[nt2][0] * inv0, O[nt2][1] * inv0);
        *(float2*)&d1[8 * nt2 + 2 * t] = make_float2(O[nt2][2] * inv1, O[nt2][3] * inv1);
    }
    if (t == 0) { d0[128] = ax0 * inv0; d1[128] = ax1 * inv1; }
}

// ---------------- K4: attention MLP + skip; pre-transposed tf32 W copy ----------------
#define MLP_A_OFF 0                         // u32[32*140] = 17920 (aliased as Hs after GEMM1)
#define MLP_W_OFF 17920                     // u32[136*140] = 76160
#define MLP_B_OFF (17920 + 76160)           // f32[272]
#define SMEM_MLP (MLP_B_OFF + 272 * 4)

__global__ void __launch_bounds__(256, 2) k_mlp(const float* __restrict__ b1, const float* __restrict__ b2) {
    extern __shared__ char smc[];
    uint32_t* As = (uint32_t*)(smc + MLP_A_OFF);
    uint32_t* Ws = (uint32_t*)(smc + MLP_W_OFF);
    float* bias_s = (float*)(smc + MLP_B_OFF);
    int blk = blockIdx.x, tid = threadIdx.x;
    int w = tid >> 5, lane = tid & 31, g = lane >> 2, t = lane & 3;
    int wm = w & 1, wn = w >> 1;
    int m0 = wm * 16;
    int NT = wn ? 4 : 5;
    int ntb = wn ? (4 * wn + 1) : 0;

    for (int e = tid; e < 272; e += 256) {
        float bval = 0.f;
        if (e < 129) bval = b1[e];
        else if (e >= 136 && e < 265) bval = b2[e - 136];
        bias_s[e] = bval;
    }
    for (int e = tid; e < 32 * 140; e += 256) {
        int u = e - (e / 140) * 140;
        if (u >= 129) As[e] = 0;
    }
    for (int e = tid; e < 136 * 140; e += 256) {
        int n = e / 140, u = e - n * 140;
        if (n >= 129 || u >= 132) Ws[e] = 0;
    }

    float areg[17];
    auto ldA = [&](int kc) {
        #pragma unroll
        for (int it = 0; it < 17; it++) {
            int e = tid + 256 * it;
            if (e < 4128) {
                int r = e / 129, u = e - r * 129;
                areg[it] = g_hp[((size_t)(blk * 32 + r) * 4 + kc) * 132 + u];
            }
        }
    };
    auto stA = [&]() {
        #pragma unroll
        for (int it = 0; it < 17; it++) {
            int e = tid + 256 * it;
            if (e < 4128) {
                int r = e / 129, u = e - r * 129;
                As[r * 140 + u] = to_tf32(areg[it]);
            }
        }
    };
    auto fillW = [&](const uint32_t* Wt) {
        for (int e = tid; e < 129 * 132; e += 256) {
            int n = e / 132, u = e - n * 132;
            Ws[n * 140 + u] = Wt[e];
        }
    };

    float acc[5][4];
    #pragma unroll
    for (int i = 0; i < 5; i++) { acc[i][0] = acc[i][1] = acc[i][2] = acc[i][3] = 0.f; }

    ldA(0);
    stA();
    fillW(g_w1t);
    __syncthreads();

    for (int kc = 0; kc < 4; kc++) {
        if (kc < 3) ldA(kc + 1);
        #pragma unroll
        for (int ks = 0; ks < 17; ks++) {
            uint32_t a0 = As[(m0 + g) * 140 + 8 * ks + t];
            uint32_t a1 = As[(m0 + g + 8) * 140 + 8 * ks + t];
            uint32_t a2 = As[(m0 + g) * 140 + 8 * ks + t + 4];
            uint32_t a3 = As[(m0 + g + 8) * 140 + 8 * ks + t + 4];
            #pragma unroll
            for (int i = 0; i < 5; i++) {
                if (i >= NT) break;
                int nt = ntb + i;
                uint32_t b0 = Ws[(8 * nt + g) * 140 + 8 * ks + t];
                uint32_t b1r = Ws[(8 * nt + g) * 140 + 8 * ks + t + 4];
                mma_tf32(acc[i], a0, a1, a2, a3, b0, b1r);
            }
        }
        __syncthreads();
        if (kc < 3) {
            stA();
            fillW(g_w1t + (kc + 1) * 129 * 132);
            __syncthreads();
        }
    }
    uint32_t* Hs = As;
    #pragma unroll
    for (int i = 0; i < 5; i++) {
        if (i >= NT) break;
        int nt = ntb + i;
        int col = 8 * nt + 2 * t;
        if (col <= 128) {
            Hs[(m0 + g) * 140 + col]     = to_tf32(fmaxf(acc[i][0] + bias_s[col], 0.f));
            Hs[(m0 + g + 8) * 140 + col] = to_tf32(fmaxf(acc[i][2] + bias_s[col], 0.f));
        }
        if (col + 1 <= 128) {
            Hs[(m0 + g) * 140 + col + 1]     = to_tf32(fmaxf(acc[i][1] + bias_s[col + 1], 0.f));
            Hs[(m0 + g + 8) * 140 + col + 1] = to_tf32(fmaxf(acc[i][3] + bias_s[col + 1], 0.f));
        }
        acc[i][0] = acc[i][1] = acc[i][2] = acc[i][3] = 0.f;
    }
    __syncthreads();
    fillW(g_w2t);
    __syncthreads();
    #pragma unroll
    for (int ks = 0; ks < 17; ks++) {
        uint32_t a0 = Hs[(m0 + g) * 140 + 8 * ks + t];
        uint32_t a1 = Hs[(m0 + g + 8) * 140 + 8 * ks + t];
        uint32_t a2 = Hs[(m0 + g) * 140 + 8 * ks + t + 4];
        uint32_t a3 = Hs[(m0 + g + 8) * 140 + 8 * ks + t + 4];
        #pragma unroll
        for (int i = 0; i < 5; i++) {
            if (i >= NT) break;
            int nt = ntb + i;
            uint32_t b0 = Ws[(8 * nt + g) * 140 + 8 * ks + t];
            uint32_t b1r = Ws[(8 * nt + g) * 140 + 8 * ks + t + 4];
            mma_tf32(acc[i], a0, a1, a2, a3, b0, b1r);
        }
    }
    #pragma unroll
    for (int i = 0; i < 5; i++) {
        if (i >= NT) break;
        int nt = ntb + i;
        int col = 8 * nt + 2 * t;
        if (col <= 128) {
            int idx = (blk * 32 + m0 + g) * Cc + col;
            g_combined[idx]          += acc[i][0] + bias_s[136 + col];
            g_combined[idx + 8 * Cc] += acc[i][2] + bias_s[136 + col];
        }
        if (col + 1 <= 128) {
            int idx = (blk * 32 + m0 + g) * Cc + col + 1;
            g_combined[idx]          += acc[i][1] + bias_s[137 + col];
            g_combined[idx + 8 * Cc] += acc[i][3] + bias_s[137 + col];
        }
    }
}

// ---------------- K5: r,u gates; on-the-fly A, double-buffered W, 1 sync/iter ----------------
__global__ void __launch_bounds__(256, 2) k_gate_ru(const float* __restrict__ qv,
                                                    const int* __restrict__ nodes_b, const int* __restrict__ nodes_n,
                                                    const float* __restrict__ Wr, const float* __restrict__ br,
                                                    const float* __restrict__ Wu, const float* __restrict__ bu,
                                                    const float* __restrict__ x, const float* __restrict__ hin) {
    extern __shared__ float sm[];
    float*    sel_s = sm;                              // [32][132]
    float*    qv_s  = sel_s + 32 * 132;                // [32][33]
    uint32_t* Ws    = (uint32_t*)(qv_s + 32 * 33);     // [2 buf][2 mat][129][36]
    float*    bs    = (float*)(Ws + 2 * 2 * 129 * 36); // [2][32][34]
    int blk = blockIdx.x, nh = blockIdx.y, tid = threadIdx.x;
    int ob = nh * 32;
    int w = tid >> 5, lane = tid & 31;
    int g = lane >> 2, t = lane & 3;
    int mt = w & 1, mat = (w >> 1) & 1, nsub = w >> 2;
    int m0 = mt * 16, n0l = nsub * 16;

    for (int e = tid; e < 32 * 132; e += 256) {
        int lm = e / 132, i = e - lm * 132;
        int gm = blk * 32 + lm;
        int node = nodes_b[gm] * Nn + nodes_n[gm];
        sel_s[e] = (i < Cc) ? g_combined[node * Cc + i] : 0.f;
    }
    for (int e = tid; e < 32 * 32; e += 256) {
        int lm = e >> 5, d = e & 31;
        qv_s[lm * 33 + d] = qv[(blk * 32 + lm) * 32 + d];
    }
    for (int e = tid; e < 2048; e += 256) {
        int m2 = e >> 10, r2 = e & 1023;
        int d2 = r2 >> 5, o = r2 & 31;
        bs[m2 * 1088 + d2 * 34 + o] = (m2 ? bu : br)[d2 * 64 + ob + o];
    }

    float wreg[33];
    auto ldW = [&](int d) {
        #pragma unroll
        for (int it = 0; it < 33; it++) {
            int e = tid + 256 * it;
            if (e < 8256) {
                int m2 = (e >= 4128);
                int e2 = e - m2 * 4128;
                int k = e2 >> 5, o = e2 & 31;
                wreg[it] = (m2 ? Wu : Wr)[((size_t)d * Cc + k) * 64 + ob + o];
            }
        }
    };
    auto stW = [&](int buf) {
        #pragma unroll
        for (int it = 0; it < 33; it++) {
            int e = tid + 256 * it;
            if (e < 8256) {
                int m2 = (e >= 4128);
                int e2 = e - m2 * 4128;
                int k = e2 >> 5, o = e2 & 31;
                Ws[buf * 9288 + m2 * 4644 + k * 36 + o] = to_tf32(wreg[it]);
            }
        }
    };

    ldW(0);
    stW(0);
    __syncthreads();

    float acc[2][4] = {};
    const int selr0 = (m0 + g) * 132, selr1 = (m0 + g + 8) * 132;
    const int qvr0 = (m0 + g) * 33,  qvr1 = (m0 + g + 8) * 33;

    for (int d = 0; d < 32; d++) {
        if (d < 31) ldW(d + 1);
        float q0 = qv_s[qvr0 + d];
        float q1 = qv_s[qvr1 + d];
        const uint32_t* Wm = Ws + (d & 1) * 9288 + mat * 4644;
        #pragma unroll 4
        for (int ks = 0; ks < 16; ks++) {
            int k0 = ks * 8;
            uint32_t a0 = to_tf32(q0 * sel_s[selr0 + k0 + t]);
            uint32_t a1 = to_tf32(q1 * sel_s[selr1 + k0 + t]);
            uint32_t a2 = to_tf32(q0 * sel_s[selr0 + k0 + t + 4]);
            uint32_t a3 = to_tf32(q1 * sel_s[selr1 + k0 + t + 4]);
            #pragma unroll
            for (int cn = 0; cn < 2; cn++) {
                uint32_t b0 = Wm[(k0 + t) * 36 + n0l + cn * 8 + g];
                uint32_t b1 = Wm[(k0 + t + 4) * 36 + n0l + cn * 8 + g];
                mma_tf32(acc[cn], a0, a1, a2, a3, b0, b1);
            }
        }
        float z0 = q0 * sel_s[selr0 + 128];
        float z1 = q1 * sel_s[selr1 + 128];
        #pragma unroll
        for (int cn = 0; cn < 2; cn++) {
            float w0 = __uint_as_float(Wm[128 * 36 + n0l + cn * 8 + 2 * t]);
            float w1 = __uint_as_float(Wm[128 * 36 + n0l + cn * 8 + 2 * t + 1]);
            acc[cn][0] += z0 * w0; acc[cn][1] += z0 * w1;
            acc[cn][2] += z1 * w0; acc[cn][3] += z1 * w1;
        }
        if (d < 31) stW((d + 1) & 1);
        __syncthreads();
    }

    const float* bm = bs + mat * 1088;
    #pragma unroll 4
    for (int d = 0; d < 32; d++) {
        float q0 = qv_s[qvr0 + d];
        float q1 = qv_s[qvr1 + d];
        #pragma unroll
        for (int cn = 0; cn < 2; cn++) {
            float w0 = bm[d * 34 + n0l + cn * 8 + 2 * t];
            float w1 = bm[d * 34 + n0l + cn * 8 + 2 * t + 1];
            acc[cn][0] += q0 * w0; acc[cn][1] += q0 * w1;
            acc[cn][2] += q1 * w0; acc[cn][3] += q1 * w1;
        }
    }

    __syncthreads();
    float* stg = sel_s;
    int cb = mat * 40;
    #pragma unroll
    for (int cn = 0; cn < 2; cn++) {
        int col = cb + n0l + cn * 8 + 2 * t;
        stg[(m0 + g) * 132 + col]     = acc[cn][0];
        stg[(m0 + g) * 132 + col + 1] = acc[cn][1];
        stg[(m0 + g + 8) * 132 + col]     = acc[cn][2];
        stg[(m0 + g + 8) * 132 + col + 1] = acc[cn][3];
    }
    __syncthreads();

    for (int e = tid; e < 32 * 32; e += 256) {
        int lm = e >> 5, o = e & 31;
        int gm = blk * 32 + lm;
        int node = nodes_b[gm] * Nn + nodes_n[gm];
        float ar = stg[lm * 132 + o];
        float au = stg[lm * 132 + 40 + o];
        float hv = hin[node * 64 + ob + o];
        float r = 1.f / (1.f + __expf(-ar));
        float u = 1.f / (1.f + __expf(-au));
        float hn = r * hv;
        g_hn[gm * 64 + ob + o] = hn;
        g_u[gm * 64 + ob + o] = u;
        g_sel2[gm * Cc + 65 + ob + o] = hn;
    }
    if (nh == 0) {
        for (int e = tid; e < 32 * 65; e += 256) {
            int lm = e / 65, i = e - lm * 65;
            int gm = blk * 32 + lm;
            int node = nodes_b[gm] * Nn + nodes_n[gm];
            g_sel2[gm * Cc + i] = x[node * 65 + i];
        }
    }
}

// ---------------- K6: cand gate; on-the-fly A, double-buffered W, 1 sync/iter ----------------
__global__ void __launch_bounds__(128, 3) k_gate_c(const float* __restrict__ qv,
                                                   const float* __restrict__ Wc, const float* __restrict__ bc,
                                                   float* __restrict__ out) {
    extern __shared__ float sm[];
    float*    sel_s = sm;                              // [32][132]
    float*    qv_s  = sel_s + 32 * 132;                // [32][33]
    uint32_t* Ws    = (uint32_t*)(qv_s + 32 * 33);     // [2 buf][129][36]
    float*    bs    = (float*)(Ws + 2 * 129 * 36);     // [32][34]
    int blk = blockIdx.x, nh = blockIdx.y, tid = threadIdx.x;
    int ob = nh * 32;
    int w = tid >> 5, lane = tid & 31;
    int g = lane >> 2, t = lane & 3;
    int mt = w & 1, nsub = w >> 1;
    int m0 = mt * 16, n0l = nsub * 16;

    for (int e = tid; e < 32 * 132; e += 128) {
        int lm = e / 132, i = e - lm * 132;
        sel_s[e] = (i < Cc) ? g_sel2[(blk * 32 + lm) * Cc + i] : 0.f;
    }
    for (int e = tid; e < 32 * 32; e += 128) {
        int lm = e >> 5, d = e & 31;
        qv_s[lm * 33 + d] = qv[(blk * 32 + lm) * 32 + d];
    }
    for (int e = tid; e < 1024; e += 128) {
        int d2 = e >> 5, o = e & 31;
        bs[d2 * 34 + o] = bc[d2 * 64 + ob + o];
    }

    float wreg[33];
    auto ldW = [&](int d) {
        #pragma unroll
        for (int it = 0; it < 33; it++) {
            int e = tid + 128 * it;
            if (e < 4128) {
                int k = e >> 5, o = e & 31;
                wreg[it] = Wc[((size_t)d * Cc + k) * 64 + ob + o];
            }
        }
    };
    auto stW = [&](int buf) {
        #pragma unroll
        for (int it = 0; it < 33; it++) {
            int e = tid + 128 * it;
            if (e < 4128) {
                int k = e >> 5, o = e & 31;
                Ws[buf * 4644 + k * 36 + o] = to_tf32(wreg[it]);
            }
        }
    };

    ldW(0);
    stW(0);
    __syncthreads();

    float acc[2][4] = {};
    const int selr0 = (m0 + g) * 132, selr1 = (m0 + g + 8) * 132;
    const int qvr0 = (m0 + g) * 33,  qvr1 = (m0 + g + 8) * 33;

    for (int d = 0; d < 32; d++) {
        if (d < 31) ldW(d + 1);
        float q0 = qv_s[qvr0 + d];
        float q1 = qv_s[qvr1 + d];
        const uint32_t* Wm = Ws + (d & 1) * 4644;
        #pragma unroll 4
        for (int ks = 0; ks < 16; ks++) {
            int k0 = ks * 8;
            uint32_t a0 = to_tf32(q0 * sel_s[selr0 + k0 + t]);
            uint32_t a1 = to_tf32(q1 * sel_s[selr1 + k0 + t]);
            uint32_t a2 = to_tf32(q0 * sel_s[selr0 + k0 + t + 4]);
            uint32_t a3 = to_tf32(q1 * sel_s[selr1 + k0 + t + 4]);
            #pragma unroll
            for (int cn = 0; cn < 2; cn++) {
                uint32_t b0 = Wm[(k0 + t) * 36 + n0l + cn * 8 + g];
                uint32_t b1 = Wm[(k0 + t + 4) * 36 + n0l + cn * 8 + g];
                mma_tf32(acc[cn], a0, a1, a2, a3, b0, b1);
            }
        }
        float z0 = q0 * sel_s[selr0 + 128];
        float z1 = q1 * sel_s[selr1 + 128];
        #pragma unroll
        for (int cn = 0; cn < 2; cn++) {
            float w0 = __uint_as_float(Wm[128 * 36 + n0l + cn * 8 + 2 * t]);
            float w1 = __uint_as_float(Wm[128 * 36 + n0l + cn * 8 + 2 * t + 1]);
            acc[cn][0] += z0 * w0; acc[cn][1] += z0 * w1;
            acc[cn][2] += z1 * w0; acc[cn][3] += z1 * w1;
        }
        if (d < 31) stW((d + 1) & 1);
        __syncthreads();
    }

    #pragma unroll 4
    for (int d = 0; d < 32; d++) {
        float q0 = qv_s[qvr0 + d];
        float q1 = qv_s[qvr1 + d];
        #pragma unroll
        for (int cn = 0; cn < 2; cn++) {
            float w0 = bs[d * 34 + n0l + cn * 8 + 2 * t];
            float w1 = bs[d * 34 + n0l + cn * 8 + 2 * t + 1];
            acc[cn][0] += q0 * w0; acc[cn][1] += q0 * w1;
            acc[cn][2] += q1 * w0; acc[cn][3] += q1 * w1;
        }
    }

    int gm0 = blk * 32 + m0 + g;
    int gm1 = gm0 + 8;
    #pragma unroll
    for (int cn = 0; cn < 2; cn++) {
        int col = ob + n0l + cn * 8 + 2 * t;
        #pragma unroll
        for (int jj = 0; jj < 2; jj++) {
            int gm = jj ? gm1 : gm0;
            float c0 = acc[cn][2 * jj], c1 = acc[cn][2 * jj + 1];
            float u0 = g_u[gm * 64 + col],     hn0 = g_hn[gm * 64 + col];
            float u1 = g_u[gm * 64 + col + 1], hn1 = g_hn[gm * 64 + col + 1];
            out[gm * 64 + col]     = (1.f - u0) * hn0 + u0 * tanhf(c0);
            out[gm * 64 + col + 1] = (1.f - u1) * hn1 + u1 * tanhf(c1);
        }
    }
}

// ---------------- launch ----------------
extern "C" void kernel_launch(void* const* d_in, const int* in_sizes, int n_in,
                              void* d_out, int out_size) {
    const float* x   = (const float*)d_in[0];
    const float* h   = (const float*)d_in[1];
    const float* qv  = (const float*)d_in[2];
    const int*   adj = (const int*)  d_in[3];
    const int*   nb  = (const int*)  d_in[4];
    const int*   nn  = (const int*)  d_in[5];
    const float* Wq  = (const float*)d_in[6];
    const float* bq  = (const float*)d_in[7];
    const float* Wk  = (const float*)d_in[8];
    const float* bk  = (const float*)d_in[9];
    const float* Wv  = (const float*)d_in[10];
    const float* bv  = (const float*)d_in[11];
    const float* W1  = (const float*)d_in[12];
    const float* b1  = (const float*)d_in[13];
    const float* W2  = (const float*)d_in[14];
    const float* b2  = (const float*)d_in[15];
    const float* Wr  = (const float*)d_in[16];
    const float* br  = (const float*)d_in[17];
    const float* Wu  = (const float*)d_in[18];
    const float* bu  = (const float*)d_in[19];
    const float* Wc  = (const float*)d_in[20];
    const float* bc  = (const float*)d_in[21];
    float* out = (float*)d_out;

    const int SZ_RU = (32 * 132 + 32 * 33 + 2 * 2 * 129 * 36 + 2 * 32 * 34 + 16) * 4;
    const int SZ_C  = (32 * 132 + 32 * 33 + 2 * 129 * 36 + 32 * 34 + 16) * 4;

    cudaFuncSetAttribute(k_qkv,      cudaFuncAttributeMaxDynamicSharedMemorySize, SMEM_QKV);
    cudaFuncSetAttribute(k_attn_mma, cudaFuncAttributeMaxDynamicSharedMemorySize, SMEM_ATT);
    cudaFuncSetAttribute(k_mlp,      cudaFuncAttributeMaxDynamicSharedMemorySize, SMEM_MLP);
    cudaFuncSetAttribute(k_gate_ru,  cudaFuncAttributeMaxDynamicSharedMemorySize, SZ_RU);
    cudaFuncSetAttribute(k_gate_c,   cudaFuncAttributeMaxDynamicSharedMemorySize, SZ_C);

    k_adjpack<<<(Nn * Nn) / 256, 256>>>(adj);
    k_wprep<<<(5 * 129 * 132 + 255) / 256, 256>>>(W1, W2);
    k_qkv<<<dim3(128, 4), 256, SMEM_QKV>>>(x, h, Wv, bv, Wq, bq, Wk, bk);
    k_attn_mma<<<dim3(16, 8, 4), 128, SMEM_ATT>>>();
    k_mlp<<<256, 256, SMEM_MLP>>>(b1, b2);
    k_gate_ru<<<dim3(128, 2), 256, SZ_RU>>>(qv, nb, nn, Wr, br, Wu, bu, x, h);
    k_gate_c<<<dim3(128, 2), 128, SZ_C>>>(qv, Wc, bc, out);
}

// round 17
// speedup vs baseline: 1.1451x; 1.0156x over previous
#include <cuda_runtime.h>
#include <cuda_bf16.h>
#include <cstdint>
#include <math.h>

#define Bb   8
#define Nn   1024
#define Dd   64
#define Hh   4
#define Cc   129
#define Kk   16
#define Mm   4096
#define ROWS 8192   // B*N

// ---------------- helpers ----------------
__device__ __forceinline__ uint32_t cvt_bf16x2(float hi, float lo) {
    uint32_t r;
    asm("cvt.rn.bf16x2.f32 %0, %1, %2;" : "=r"(r) : "f"(hi), "f"(lo));
    return r;
}
__device__ __forceinline__ uint32_t to_tf32(float f) {
    uint32_t r;
    asm("cvt.rna.tf32.f32 %0, %1;" : "=r"(r) : "f"(f));
    return r;
}
__device__ __forceinline__ void mma_bf16(float c[4], uint32_t a0, uint32_t a1, uint32_t a2, uint32_t a3,
                                         uint32_t b0, uint32_t b1) {
    asm volatile("mma.sync.aligned.m16n8k16.row.col.f32.bf16.bf16.f32 "
                 "{%0,%1,%2,%3}, {%4,%5,%6,%7}, {%8,%9}, {%0,%1,%2,%3};"
                 : "+f"(c[0]), "+f"(c[1]), "+f"(c[2]), "+f"(c[3])
                 : "r"(a0), "r"(a1), "r"(a2), "r"(a3), "r"(b0), "r"(b1));
}
__device__ __forceinline__ void mma_tf32(float c[4], uint32_t a0, uint32_t a1, uint32_t a2, uint32_t a3,
                                         uint32_t b0, uint32_t b1) {
    asm volatile("mma.sync.aligned.m16n8k8.row.col.f32.tf32.tf32.f32 "
                 "{%0,%1,%2,%3}, {%4,%5,%6,%7}, {%8,%9}, {%0,%1,%2,%3};"
                 : "+f"(c[0]), "+f"(c[1]), "+f"(c[2]), "+f"(c[3])
                 : "r"(a0), "r"(a1), "r"(a2), "r"(a3), "r"(b0), "r"(b1));
}
__device__ __forceinline__ float ex2_approx(float x) {
    float r;
    asm("ex2.approx.ftz.f32 %0, %1;" : "=f"(r) : "f"(x));
    return r;
}
// leaky(0.25*s) then exp, folded: 0.25*log2e, 0.05*log2e
__device__ __forceinline__ float expleaky(float s, uint32_t bit) {
    float s2 = s > 0.f ? s * 0.36067376f : s * 0.07213475f;
    return bit ? ex2_approx(s2) : 0.f;
}

// ================= scratch =================
__device__ float g_combined[ROWS * Cc];
__device__ __nv_bfloat16 g_qb[Hh * ROWS * Kk];
__device__ __nv_bfloat16 g_kb[Hh * ROWS * Kk];
__device__ __nv_bfloat16 g_vtb[Hh * Bb * 128 * 1024];   // [h*8+b][c<128][m]
__device__ float g_v128[Hh * Bb * 1024];                // v col 128
__device__ uint32_t g_adjbits[Nn * 32];
__device__ float g_hp[ROWS * 4 * 132];                  // [row][h][132 padded], tf32-rounded
__device__ float g_hn[Mm * Dd];
__device__ float g_u[Mm * Dd];
__device__ float g_sel2[Mm * Cc];
__device__ uint32_t g_w1t[4 * 129 * 132];               // tf32, transposed [kc][n][u]
__device__ uint32_t g_w2t[129 * 132];

// ---------------- K0b: pack adjacency bits ----------------
__global__ void k_adjpack(const int* __restrict__ adj) {
    int idx = blockIdx.x * 256 + threadIdx.x;
    uint32_t bits = __ballot_sync(0xFFFFFFFFu, adj[idx] != 0);
    if ((idx & 31) == 0) g_adjbits[idx >> 5] = bits;
}

// ---------------- K0c: pre-transpose W1/W2 to tf32 ----------------
__global__ void k_wprep(const float* __restrict__ W1, const float* __restrict__ W2) {
    int idx = blockIdx.x * 256 + threadIdx.x;
    if (idx >= 5 * 129 * 132) return;
    int m = idx / (129 * 132);
    int r = idx - m * (129 * 132);
    int n = r / 132, u = r - n * 132;
    uint32_t v = 0;
    if (u < 129)
        v = to_tf32(m < 4 ? W1[((size_t)m * 129 + u) * 129 + n]
                          : W2[(size_t)u * 129 + n]);
    if (m < 4) g_w1t[idx] = v;
    else       g_w2t[r] = v;
}

// ---------------- K1: fused concat + q/k/v projections via bf16 mma ----------------
#define QKV_AB_OFF 0
#define QKV_WT_OFF 19456
#define QKV_BS_OFF (19456 + 53504)
#define SMEM_QKV (QKV_BS_OFF + 176 * 4)

__global__ void __launch_bounds__(256, 2) k_qkv(const float* __restrict__ x, const float* __restrict__ h,
                                                const float* __restrict__ Wv, const float* __restrict__ bv,
                                                const float* __restrict__ Wq, const float* __restrict__ bq,
                                                const float* __restrict__ Wk, const float* __restrict__ bk) {
    extern __shared__ char smc[];
    uint32_t* Ab = (uint32_t*)(smc + QKV_AB_OFF);
    uint32_t* Wt = (uint32_t*)(smc + QKV_WT_OFF);
    float* bias_s = (float*)(smc + QKV_BS_OFF);
    int tile = blockIdx.x, hh = blockIdx.y, tid = threadIdx.x;
    int w = tid >> 5, lane = tid & 31, g = lane >> 2, t = lane & 3;
    int wm = w & 3, wn = w >> 2;
    int m0 = wm * 16;

    for (int e = tid; e < 64 * 76; e += 256) {
        int r = e / 76, u = e - r * 76;
        int row = tile * 64 + r;
        uint32_t val = 0;
        if (u < 65) {
            int c0 = 2 * u, c1 = 2 * u + 1;
            float f0 = (c0 < 65) ? x[row * 65 + c0] : h[row * 64 + (c0 - 65)];
            float f1 = 0.f;
            if (c1 < 129) f1 = (c1 < 65) ? x[row * 65 + c1] : h[row * 64 + (c1 - 65)];
            val = cvt_bf16x2(f1, f0);
            if (hh == 0) {
                g_combined[row * Cc + c0] = f0;
                if (c1 < 129) g_combined[row * Cc + c1] = f1;
            }
        }
        Ab[e] = val;
    }
    const float* wvh = Wv + (size_t)hh * 129 * 129;
    const float* wqh = Wq + (size_t)hh * 129 * 16;
    const float* wkh = Wk + (size_t)hh * 129 * 16;
    for (int e = tid; e < 76 * 176; e += 256) {
        int u = e / 176, n = e - u * 176;
        float w0 = 0.f, w1 = 0.f;
        if (u < 65) {
            int k0 = 2 * u, k1 = 2 * u + 1;
            if (n < 129) {
                w0 = wvh[k0 * 129 + n];
                if (k1 < 129) w1 = wvh[k1 * 129 + n];
            } else if (n >= 136 && n < 152) {
                int kk = n - 136;
                w0 = wqh[k0 * 16 + kk];
                if (k1 < 129) w1 = wqh[k1 * 16 + kk];
            } else if (n >= 152 && n < 168) {
                int kk = n - 152;
                w0 = wkh[k0 * 16 + kk];
                if (k1 < 129) w1 = wkh[k1 * 16 + kk];
            }
        }
        Wt[n * 76 + u] = cvt_bf16x2(w1, w0);
    }
    for (int e = tid; e < 176; e += 256) {
        float bval = 0.f;
        if (e < 129) bval = bv[hh * 129 + e];
        else if (e >= 136 && e < 152) bval = bq[hh * 16 + e - 136];
        else if (e >= 152 && e < 168) bval = bk[hh * 16 + e - 152];
        bias_s[e] = bval;
    }
    __syncthreads();

    float acc[11][4];
    #pragma unroll
    for (int i = 0; i < 11; i++) { acc[i][0] = acc[i][1] = acc[i][2] = acc[i][3] = 0.f; }
    int ntb = wn * 11;

    #pragma unroll
    for (int ks = 0; ks < 9; ks++) {
        uint32_t a0 = Ab[(m0 + g) * 76 + 8 * ks + t];
        uint32_t a1 = Ab[(m0 + g + 8) * 76 + 8 * ks + t];
        uint32_t a2 = Ab[(m0 + g) * 76 + 8 * ks + t + 4];
        uint32_t a3 = Ab[(m0 + g + 8) * 76 + 8 * ks + t + 4];
        #pragma unroll
        for (int i = 0; i < 11; i++) {
            int nt = ntb + i;
            uint32_t b0 = Wt[(8 * nt + g) * 76 + 8 * ks + t];
            uint32_t b1 = Wt[(8 * nt + g) * 76 + 8 * ks + t + 4];
            mma_bf16(acc[i], a0, a1, a2, a3, b0, b1);
        }
    }

    size_t rowbase = (size_t)hh * ROWS + tile * 64 + m0;
    if (wn == 1) {
        #pragma unroll
        for (int i = 6; i < 10; i++) {
            int nt = 11 + i;
            bool isq = nt < 19;
            int col = (nt - (isq ? 17 : 19)) * 8 + 2 * t;
            float b0v = bias_s[(isq ? 136 : 152) + col];
            float b1v = bias_s[(isq ? 136 : 152) + col + 1];
            __nv_bfloat16* dst = isq ? g_qb : g_kb;
            *(uint32_t*)&dst[(rowbase + g) * 16 + col] =
                cvt_bf16x2(acc[i][1] + b1v, acc[i][0] + b0v);
            *(uint32_t*)&dst[(rowbase + g + 8) * 16 + col] =
                cvt_bf16x2(acc[i][3] + b1v, acc[i][2] + b0v);
        }
    }
    __syncthreads();
    float* vtile = (float*)smc;
    #pragma unroll
    for (int i = 0; i < 11; i++) {
        int nt = ntb + i;
        if (nt > 16) break;
        int col = 8 * nt + 2 * t;
        if (col <= 128) {
            float bb = bias_s[col];
            vtile[(m0 + g) * 132 + col]     = acc[i][0] + bb;
            vtile[(m0 + g + 8) * 132 + col] = acc[i][2] + bb;
        }
        if (col + 1 <= 128) {
            float bb = bias_s[col + 1];
            vtile[(m0 + g) * 132 + col + 1]     = acc[i][1] + bb;
            vtile[(m0 + g + 8) * 132 + col + 1] = acc[i][3] + bb;
        }
    }
    __syncthreads();

    int b_idx = tile >> 4;
    int mbase = (tile & 15) * 64;
    size_t hb = hh * 8 + b_idx;
    for (int e = tid; e < 128 * 32; e += 256) {
        int c = e >> 5, mp = e & 31;
        float f0 = vtile[(mp * 2) * 132 + c];
        float f1 = vtile[(mp * 2 + 1) * 132 + c];
        *(__nv_bfloat162*)&g_vtb[(hb * 128 + c) * 1024 + mbase + mp * 2] =
            __float22bfloat162_rn(make_float2(f0, f1));
    }
    if (tid < 64)
        g_v128[hb * 1024 + mbase + tid] = vtile[tid * 132 + 128];
}

// ---------------- K3: HMMA flash attention, 64-row CTAs, 2 CTA/SM ----------------
#define AKS_OFF 0
#define AVT_OFF 6144
#define AV1_OFF (6144 + 34816)
#define SMEM_ATT (AV1_OFF + 512)

__global__ void __launch_bounds__(128, 2) k_attn_mma() {
    extern __shared__ char smc[];
    uint32_t* Ks  = (uint32_t*)(smc + AKS_OFF);
    uint32_t* VTs = (uint32_t*)(smc + AVT_OFF);
    float*    v1s = (float*)(smc + AV1_OFF);
    int tid = threadIdx.x, w = tid >> 5, lane = tid & 31;
    int g = lane >> 2, t = lane & 3;
    int rblk = blockIdx.x, b = blockIdx.y, hh = blockIdx.z;
    size_t hb = hh * 8 + b;
    int brow = b * 1024 + rblk * 64;

    const __nv_bfloat16* qsrc = g_qb + ((size_t)hh * ROWS + brow + 16 * w) * 16;
    uint32_t qa0 = *(const uint32_t*)(qsrc + g * 16 + 2 * t);
    uint32_t qa1 = *(const uint32_t*)(qsrc + (g + 8) * 16 + 2 * t);
    uint32_t qa2 = *(const uint32_t*)(qsrc + g * 16 + 2 * t + 8);
    uint32_t qa3 = *(const uint32_t*)(qsrc + (g + 8) * 16 + 2 * t + 8);

    int nrow0 = rblk * 64 + 16 * w + g;
    int nrow1 = nrow0 + 8;

    float O[16][4];
    #pragma unroll
    for (int i = 0; i < 16; i++) { O[i][0] = O[i][1] = O[i][2] = O[i][3] = 0.f; }
    float rs0 = 0.f, rs1 = 0.f, ax0 = 0.f, ax1 = 0.f;

    const uint32_t* kbase = (const uint32_t*)(g_kb + ((size_t)hh * ROWS + b * 1024) * 16);
    const __nv_bfloat16* vbase = g_vtb + hb * 131072;

    for (int j = 0; j < 8; j++) {
        __syncthreads();
        const uint32_t* ks = kbase + j * 128 * 8;
        #pragma unroll
        for (int it = 0; it < 8; it++) {
            int e = tid + 128 * it;
            int r = e >> 3, c8 = e & 7;
            Ks[r * 12 + c8] = ks[e];
        }
        #pragma unroll
        for (int it = 0; it < 16; it++) {
            int e = tid + 128 * it;
            int c = e >> 4, q = e & 15;
            ((uint4*)(smc + AVT_OFF + c * 272))[q] =
                ((const uint4*)(vbase + (size_t)c * 1024 + j * 128))[q];
        }
        v1s[tid] = g_v128[hb * 1024 + j * 128 + tid];
        uint4 A0 = ((const uint4*)g_adjbits)[nrow0 * 8 + j];
        uint4 A1 = ((const uint4*)g_adjbits)[nrow1 * 8 + j];
        __syncthreads();

        uint32_t af[8][4];
        #pragma unroll
        for (int nt = 0; nt < 16; nt++) {
            uint32_t b0 = Ks[(8 * nt + g) * 12 + t];
            uint32_t b1 = Ks[(8 * nt + g) * 12 + t + 4];
            float c[4] = {0.f, 0.f, 0.f, 0.f};
            mma_bf16(c, qa0, qa1, qa2, qa3, b0, b1);
            uint32_t wA = (nt < 4) ? A0.x : (nt < 8) ? A0.y : (nt < 12) ? A0.z : A0.w;
            uint32_t wB = (nt < 4) ? A1.x : (nt < 8) ? A1.y : (nt < 12) ? A1.z : A1.w;
            int bitb = ((nt & 3) << 3) + 2 * t;
            float p00 = expleaky(c[0], (wA >> bitb) & 1);
            float p01 = expleaky(c[1], (wA >> (bitb + 1)) & 1);
            float p10 = expleaky(c[2], (wB >> bitb) & 1);
            float p11 = expleaky(c[3], (wB >> (bitb + 1)) & 1);
            rs0 += p00 + p01; rs1 += p10 + p11;
            float2 v2 = *(const float2*)&v1s[8 * nt + 2 * t];
            ax0 += p00 * v2.x + p01 * v2.y;
            ax1 += p10 * v2.x + p11 * v2.y;
            int kc = nt >> 1;
            if ((nt & 1) == 0) {
                af[kc][0] = cvt_bf16x2(p01, p00);
                af[kc][1] = cvt_bf16x2(p11, p10);
            } else {
                af[kc][2] = cvt_bf16x2(p01, p00);
                af[kc][3] = cvt_bf16x2(p11, p10);
            }
        }
        #pragma unroll
        for (int kc = 0; kc < 8; kc++) {
            #pragma unroll
            for (int nt2 = 0; nt2 < 16; nt2++) {
                uint32_t b0 = VTs[(8 * nt2 + g) * 68 + 8 * kc + t];
                uint32_t b1 = VTs[(8 * nt2 + g) * 68 + 8 * kc + t + 4];
                mma_bf16(O[nt2], af[kc][0], af[kc][1], af[kc][2], af[kc][3], b0, b1);
            }
        }
    }

    rs0 += __shfl_xor_sync(0xFFFFFFFFu, rs0, 1); rs0 += __shfl_xor_sync(0xFFFFFFFFu, rs0, 2);
    rs1 += __shfl_xor_sync(0xFFFFFFFFu, rs1, 1); rs1 += __shfl_xor_sync(0xFFFFFFFFu, rs1, 2);
    ax0 += __shfl_xor_sync(0xFFFFFFFFu, ax0, 1); ax0 += __shfl_xor_sync(0xFFFFFFFFu, ax0, 2);
    ax1 += __shfl_xor_sync(0xFFFFFFFFu, ax1, 1); ax1 += __shfl_xor_sync(0xFFFFFFFFu, ax1, 2);
    float inv0 = 1.f / rs0, inv1 = 1.f / rs1;

    // store tf32-rounded (mlp consumes tf32 anyway -> bit-identical mlp result)
    float* d0 = g_hp + ((size_t)(brow + 16 * w + g) * 4 + hh) * 132;
    float* d1 = d0 + 8 * 4 * 132;
    #pragma unroll
    for (int nt2 = 0; nt2 < 16; nt2++) {
        *(float2*)&d0[8 * nt2 + 2 * t] = make_float2(__uint_as_float(to_tf32(O[nt2][0] * inv0)),
                                                     __uint_as_float(to_tf32(O[nt2][1] * inv0)));
        *(float2*)&d1[8 * nt2 + 2 * t] = make_float2(__uint_as_float(to_tf32(O[nt2][2] * inv1)),
                                                     __uint_as_float(to_tf32(O[nt2][3] * inv1)));
    }
    if (t == 0) {
        d0[128] = __uint_as_float(to_tf32(ax0 * inv0));
        d1[128] = __uint_as_float(to_tf32(ax1 * inv1));
    }
}

// ---------------- K4: attention MLP + skip; pre-transposed tf32 W copy ----------------
#define MLP_A_OFF 0
#define MLP_W_OFF 17920
#define MLP_B_OFF (17920 + 76160)
#define SMEM_MLP (MLP_B_OFF + 272 * 4)

__global__ void __launch_bounds__(256, 2) k_mlp(const float* __restrict__ b1, const float* __restrict__ b2) {
    extern __shared__ char smc[];
    uint32_t* As = (uint32_t*)(smc + MLP_A_OFF);
    uint32_t* Ws = (uint32_t*)(smc + MLP_W_OFF);
    float* bias_s = (float*)(smc + MLP_B_OFF);
    int blk = blockIdx.x, tid = threadIdx.x;
    int w = tid >> 5, lane = tid & 31, g = lane >> 2, t = lane & 3;
    int wm = w & 1, wn = w >> 1;
    int m0 = wm * 16;
    int NT = wn ? 4 : 5;
    int ntb = wn ? (4 * wn + 1) : 0;

    for (int e = tid; e < 272; e += 256) {
        float bval = 0.f;
        if (e < 129) bval = b1[e];
        else if (e >= 136 && e < 265) bval = b2[e - 136];
        bias_s[e] = bval;
    }
    for (int e = tid; e < 32 * 140; e += 256) {
        int u = e - (e / 140) * 140;
        if (u >= 129) As[e] = 0;
    }
    for (int e = tid; e < 136 * 140; e += 256) {
        int n = e / 140, u = e - n * 140;
        if (n >= 129 || u >= 132) Ws[e] = 0;
    }

    uint32_t areg[17];
    auto ldA = [&](int kc) {
        #pragma unroll
        for (int it = 0; it < 17; it++) {
            int e = tid + 256 * it;
            if (e < 4128) {
                int r = e / 129, u = e - r * 129;
                areg[it] = __float_as_uint(g_hp[((size_t)(blk * 32 + r) * 4 + kc) * 132 + u]);
            }
        }
    };
    auto stA = [&]() {
        #pragma unroll
        for (int it = 0; it < 17; it++) {
            int e = tid + 256 * it;
            if (e < 4128) {
                int r = e / 129, u = e - r * 129;
                As[r * 140 + u] = areg[it];   // already tf32-rounded by attn
            }
        }
    };
    auto fillW = [&](const uint32_t* Wt) {
        for (int e = tid; e < 129 * 132; e += 256) {
            int n = e / 132, u = e - n * 132;
            Ws[n * 140 + u] = Wt[e];
        }
    };

    float acc[5][4];
    #pragma unroll
    for (int i = 0; i < 5; i++) { acc[i][0] = acc[i][1] = acc[i][2] = acc[i][3] = 0.f; }

    ldA(0);
    stA();
    fillW(g_w1t);
    __syncthreads();

    for (int kc = 0; kc < 4; kc++) {
        if (kc < 3) ldA(kc + 1);
        #pragma unroll
        for (int ks = 0; ks < 17; ks++) {
            uint32_t a0 = As[(m0 + g) * 140 + 8 * ks + t];
            uint32_t a1 = As[(m0 + g + 8) * 140 + 8 * ks + t];
            uint32_t a2 = As[(m0 + g) * 140 + 8 * ks + t + 4];
            uint32_t a3 = As[(m0 + g + 8) * 140 + 8 * ks + t + 4];
            #pragma unroll
            for (int i = 0; i < 5; i++) {
                if (i >= NT) break;
                int nt = ntb + i;
                uint32_t b0 = Ws[(8 * nt + g) * 140 + 8 * ks + t];
                uint32_t b1r = Ws[(8 * nt + g) * 140 + 8 * ks + t + 4];
                mma_tf32(acc[i], a0, a1, a2, a3, b0, b1r);
            }
        }
        __syncthreads();
        if (kc < 3) {
            stA();
            fillW(g_w1t + (kc + 1) * 129 * 132);
            __syncthreads();
        }
    }
    uint32_t* Hs = As;
    #pragma unroll
    for (int i = 0; i < 5; i++) {
        if (i >= NT) break;
        int nt = ntb + i;
        int col = 8 * nt + 2 * t;
        if (col <= 128) {
            Hs[(m0 + g) * 140 + col]     = to_tf32(fmaxf(acc[i][0] + bias_s[col], 0.f));
            Hs[(m0 + g + 8) * 140 + col] = to_tf32(fmaxf(acc[i][2] + bias_s[col], 0.f));
        }
        if (col + 1 <= 128) {
            Hs[(m0 + g) * 140 + col + 1]     = to_tf32(fmaxf(acc[i][1] + bias_s[col + 1], 0.f));
            Hs[(m0 + g + 8) * 140 + col + 1] = to_tf32(fmaxf(acc[i][3] + bias_s[col + 1], 0.f));
        }
        acc[i][0] = acc[i][1] = acc[i][2] = acc[i][3] = 0.f;
    }
    __syncthreads();
    fillW(g_w2t);
    __syncthreads();
    #pragma unroll
    for (int ks = 0; ks < 17; ks++) {
        uint32_t a0 = Hs[(m0 + g) * 140 + 8 * ks + t];
        uint32_t a1 = Hs[(m0 + g + 8) * 140 + 8 * ks + t];
        uint32_t a2 = Hs[(m0 + g) * 140 + 8 * ks + t + 4];
        uint32_t a3 = Hs[(m0 + g + 8) * 140 + 8 * ks + t + 4];
        #pragma unroll
        for (int i = 0; i < 5; i++) {
            if (i >= NT) break;
            int nt = ntb + i;
            uint32_t b0 = Ws[(8 * nt + g) * 140 + 8 * ks + t];
            uint32_t b1r = Ws[(8 * nt + g) * 140 + 8 * ks + t + 4];
            mma_tf32(acc[i], a0, a1, a2, a3, b0, b1r);
        }
    }
    #pragma unroll
    for (int i = 0; i < 5; i++) {
        if (i >= NT) break;
        int nt = ntb + i;
        int col = 8 * nt + 2 * t;
        if (col <= 128) {
            int idx = (blk * 32 + m0 + g) * Cc + col;
            g_combined[idx]          += acc[i][0] + bias_s[136 + col];
            g_combined[idx + 8 * Cc] += acc[i][2] + bias_s[136 + col];
        }
        if (col + 1 <= 128) {
            int idx = (blk * 32 + m0 + g) * Cc + col + 1;
            g_combined[idx]          += acc[i][1] + bias_s[137 + col];
            g_combined[idx + 8 * Cc] += acc[i][3] + bias_s[137 + col];
        }
    }
}

// ---------------- K5: r,u gates; constant tf32 A, q folded post-mma ----------------
__global__ void __launch_bounds__(256, 2) k_gate_ru(const float* __restrict__ qv,
                                                    const int* __restrict__ nodes_b, const int* __restrict__ nodes_n,
                                                    const float* __restrict__ Wr, const float* __restrict__ br,
                                                    const float* __restrict__ Wu, const float* __restrict__ bu,
                                                    const float* __restrict__ x, const float* __restrict__ hin) {
    extern __shared__ float sm[];
    uint32_t* selt  = (uint32_t*)sm;                   // [32][132] tf32
    float*    qv_s  = sm + 32 * 132;                   // [32][33]
    uint32_t* Ws    = (uint32_t*)(qv_s + 32 * 33);     // [2 buf][2 mat][129][36]
    float*    bs    = (float*)(Ws + 2 * 2 * 129 * 36); // [2][32][34]
    int blk = blockIdx.x, nh = blockIdx.y, tid = threadIdx.x;
    int ob = nh * 32;
    int w = tid >> 5, lane = tid & 31;
    int g = lane >> 2, t = lane & 3;
    int mt = w & 1, mat = (w >> 1) & 1, nsub = w >> 2;
    int m0 = mt * 16, n0l = nsub * 16;

    for (int e = tid; e < 32 * 132; e += 256) {
        int lm = e / 132, i = e - lm * 132;
        int gm = blk * 32 + lm;
        int node = nodes_b[gm] * Nn + nodes_n[gm];
        selt[e] = (i < Cc) ? to_tf32(g_combined[node * Cc + i]) : 0u;
    }
    for (int e = tid; e < 32 * 32; e += 256) {
        int lm = e >> 5, d = e & 31;
        qv_s[lm * 33 + d] = qv[(blk * 32 + lm) * 32 + d];
    }
    for (int e = tid; e < 2048; e += 256) {
        int m2 = e >> 10, r2 = e & 1023;
        int d2 = r2 >> 5, o = r2 & 31;
        bs[m2 * 1088 + d2 * 34 + o] = (m2 ? bu : br)[d2 * 64 + ob + o];
    }

    float wreg[33];
    auto ldW = [&](int d) {
        #pragma unroll
        for (int it = 0; it < 33; it++) {
            int e = tid + 256 * it;
            if (e < 8256) {
                int m2 = (e >= 4128);
                int e2 = e - m2 * 4128;
                int k = e2 >> 5, o = e2 & 31;
                wreg[it] = (m2 ? Wu : Wr)[((size_t)d * Cc + k) * 64 + ob + o];
            }
        }
    };
    auto stW = [&](int buf) {
        #pragma unroll
        for (int it = 0; it < 33; it++) {
            int e = tid + 256 * it;
            if (e < 8256) {
                int m2 = (e >= 4128);
                int e2 = e - m2 * 4128;
                int k = e2 >> 5, o = e2 & 31;
                Ws[buf * 9288 + m2 * 4644 + k * 36 + o] = to_tf32(wreg[it]);
            }
        }
    };

    ldW(0);
    stW(0);
    __syncthreads();

    float acc[2][4] = {};
    const int selr0 = (m0 + g) * 132, selr1 = (m0 + g + 8) * 132;
    const int qvr0 = (m0 + g) * 33,  qvr1 = (m0 + g + 8) * 33;
    float sv0 = __uint_as_float(selt[selr0 + 128]);
    float sv1 = __uint_as_float(selt[selr1 + 128]);

    for (int d = 0; d < 32; d++) {
        if (d < 31) ldW(d + 1);
        float q0 = qv_s[qvr0 + d];
        float q1 = qv_s[qvr1 + d];
        const uint32_t* Wm = Ws + (d & 1) * 9288 + mat * 4644;
        float cc[2][4] = {};
        #pragma unroll 4
        for (int ks = 0; ks < 16; ks++) {
            int k0 = ks * 8;
            uint32_t a0 = selt[selr0 + k0 + t];
            uint32_t a1 = selt[selr1 + k0 + t];
            uint32_t a2 = selt[selr0 + k0 + t + 4];
            uint32_t a3 = selt[selr1 + k0 + t + 4];
            #pragma unroll
            for (int cn = 0; cn < 2; cn++) {
                uint32_t b0 = Wm[(k0 + t) * 36 + n0l + cn * 8 + g];
                uint32_t b1 = Wm[(k0 + t + 4) * 36 + n0l + cn * 8 + g];
                mma_tf32(cc[cn], a0, a1, a2, a3, b0, b1);
            }
        }
        // k=128 tail folded into cc (sel-scaled, q applied below)
        #pragma unroll
        for (int cn = 0; cn < 2; cn++) {
            float w0 = __uint_as_float(Wm[128 * 36 + n0l + cn * 8 + 2 * t]);
            float w1 = __uint_as_float(Wm[128 * 36 + n0l + cn * 8 + 2 * t + 1]);
            cc[cn][0] += sv0 * w0; cc[cn][1] += sv0 * w1;
            cc[cn][2] += sv1 * w0; cc[cn][3] += sv1 * w1;
            acc[cn][0] += q0 * cc[cn][0]; acc[cn][1] += q0 * cc[cn][1];
            acc[cn][2] += q1 * cc[cn][2]; acc[cn][3] += q1 * cc[cn][3];
        }
        if (d < 31) stW((d + 1) & 1);
        __syncthreads();
    }

    const float* bm = bs + mat * 1088;
    #pragma unroll 4
    for (int d = 0; d < 32; d++) {
        float q0 = qv_s[qvr0 + d];
        float q1 = qv_s[qvr1 + d];
        #pragma unroll
        for (int cn = 0; cn < 2; cn++) {
            float w0 = bm[d * 34 + n0l + cn * 8 + 2 * t];
            float w1 = bm[d * 34 + n0l + cn * 8 + 2 * t + 1];
            acc[cn][0] += q0 * w0; acc[cn][1] += q0 * w1;
            acc[cn][2] += q1 * w0; acc[cn][3] += q1 * w1;
        }
    }

    __syncthreads();
    float* stg = (float*)selt;
    int cb = mat * 40;
    #pragma unroll
    for (int cn = 0; cn < 2; cn++) {
        int col = cb + n0l + cn * 8 + 2 * t;
        stg[(m0 + g) * 132 + col]     = acc[cn][0];
        stg[(m0 + g) * 132 + col + 1] = acc[cn][1];
        stg[(m0 + g + 8) * 132 + col]     = acc[cn][2];
        stg[(m0 + g + 8) * 132 + col + 1] = acc[cn][3];
    }
    __syncthreads();

    for (int e = tid; e < 32 * 32; e += 256) {
        int lm = e >> 5, o = e & 31;
        int gm = blk * 32 + lm;
        int node = nodes_b[gm] * Nn + nodes_n[gm];
        float ar = stg[lm * 132 + o];
        float au = stg[lm * 132 + 40 + o];
        float hv = hin[node * 64 + ob + o];
        float r = 1.f / (1.f + __expf(-ar));
        float u = 1.f / (1.f + __expf(-au));
        float hn = r * hv;
        g_hn[gm * 64 + ob + o] = hn;
        g_u[gm * 64 + ob + o] = u;
        g_sel2[gm * Cc + 65 + ob + o] = hn;
    }
    if (nh == 0) {
        for (int e = tid; e < 32 * 65; e += 256) {
            int lm = e / 65, i = e - lm * 65;
            int gm = blk * 32 + lm;
            int node = nodes_b[gm] * Nn + nodes_n[gm];
            g_sel2[gm * Cc + i] = x[node * 65 + i];
        }
    }
}

// ---------------- K6: cand gate; constant tf32 A, q folded post-mma ----------------
__global__ void __launch_bounds__(128, 3) k_gate_c(const float* __restrict__ qv,
                                                   const float* __restrict__ Wc, const float* __restrict__ bc,
                                                   float* __restrict__ out) {
    extern __shared__ float sm[];
    uint32_t* selt  = (uint32_t*)sm;                   // [32][132] tf32
    float*    qv_s  = sm + 32 * 132;                   // [32][33]
    uint32_t* Ws    = (uint32_t*)(qv_s + 32 * 33);     // [2 buf][129][36]
    float*    bs    = (float*)(Ws + 2 * 129 * 36);     // [32][34]
    int blk = blockIdx.x, nh = blockIdx.y, tid = threadIdx.x;
    int ob = nh * 32;
    int w = tid >> 5, lane = tid & 31;
    int g = lane >> 2, t = lane & 3;
    int mt = w & 1, nsub = w >> 1;
    int m0 = mt * 16, n0l = nsub * 16;

    for (int e = tid; e < 32 * 132; e += 128) {
        int lm = e / 132, i = e - lm * 132;
        selt[e] = (i < Cc) ? to_tf32(g_sel2[(blk * 32 + lm) * Cc + i]) : 0u;
    }
    for (int e = tid; e < 32 * 32; e += 128) {
        int lm = e >> 5, d = e & 31;
        qv_s[lm * 33 + d] = qv[(blk * 32 + lm) * 32 + d];
    }
    for (int e = tid; e < 1024; e += 128) {
        int d2 = e >> 5, o = e & 31;
        bs[d2 * 34 + o] = bc[d2 * 64 + ob + o];
    }

    float wreg[33];
    auto ldW = [&](int d) {
        #pragma unroll
        for (int it = 0; it < 33; it++) {
            int e = tid + 128 * it;
            if (e < 4128) {
                int k = e >> 5, o = e & 31;
                wreg[it] = Wc[((size_t)d * Cc + k) * 64 + ob + o];
            }
        }
    };
    auto stW = [&](int buf) {
        #pragma unroll
        for (int it = 0; it < 33; it++) {
            int e = tid + 128 * it;
            if (e < 4128) {
                int k = e >> 5, o = e & 31;
                Ws[buf * 4644 + k * 36 + o] = to_tf32(wreg[it]);
            }
        }
    };

    ldW(0);
    stW(0);
    __syncthreads();

    float acc[2][4] = {};
    const int selr0 = (m0 + g) * 132, selr1 = (m0 + g + 8) * 132;
    const int qvr0 = (m0 + g) * 33,  qvr1 = (m0 + g + 8) * 33;
    float sv0 = __uint_as_float(selt[selr0 + 128]);
    float sv1 = __uint_as_float(selt[selr1 + 128]);

    for (int d = 0; d < 32; d++) {
        if (d < 31) ldW(d + 1);
        float q0 = qv_s[qvr0 + d];
        float q1 = qv_s[qvr1 + d];
        const uint32_t* Wm = Ws + (d & 1) * 4644;
        float cc[2][4] = {};
        #pragma unroll 4
        for (int ks = 0; ks < 16; ks++) {
            int k0 = ks * 8;
            uint32_t a0 = selt[selr0 + k0 + t];
            uint32_t a1 = selt[selr1 + k0 + t];
            uint32_t a2 = selt[selr0 + k0 + t + 4];
            uint32_t a3 = selt[selr1 + k0 + t + 4];
            #pragma unroll
            for (int cn = 0; cn < 2; cn++) {
                uint32_t b0 = Wm[(k0 + t) * 36 + n0l + cn * 8 + g];
                uint32_t b1 = Wm[(k0 + t + 4) * 36 + n0l + cn * 8 + g];
                mma_tf32(cc[cn], a0, a1, a2, a3, b0, b1);
            }
        }
        #pragma unroll
        for (int cn = 0; cn < 2; cn++) {
            float w0 = __uint_as_float(Wm[128 * 36 + n0l + cn * 8 + 2 * t]);
            float w1 = __uint_as_float(Wm[128 * 36 + n0l + cn * 8 + 2 * t + 1]);
            cc[cn][0] += sv0 * w0; cc[cn][1] += sv0 * w1;
            cc[cn][2] += sv1 * w0; cc[cn][3] += sv1 * w1;
            acc[cn][0] += q0 * cc[cn][0]; acc[cn][1] += q0 * cc[cn][1];
            acc[cn][2] += q1 * cc[cn][2]; acc[cn][3] += q1 * cc[cn][3];
        }
        if (d < 31) stW((d + 1) & 1);
        __syncthreads();
    }

    #pragma unroll 4
    for (int d = 0; d < 32; d++) {
        float q0 = qv_s[qvr0 + d];
        float q1 = qv_s[qvr1 + d];
        #pragma unroll
        for (int cn = 0; cn < 2; cn++) {
            float w0 = bs[d * 34 + n0l + cn * 8 + 2 * t];
            float w1 = bs[d * 34 + n0l + cn * 8 + 2 * t + 1];
            acc[cn][0] += q0 * w0; acc[cn][1] += q0 * w1;
            acc[cn][2] += q1 * w0; acc[cn][3] += q1 * w1;
        }
    }

    int gm0 = blk * 32 + m0 + g;
    int gm1 = gm0 + 8;
    #pragma unroll
    for (int cn = 0; cn < 2; cn++) {
        int col = ob + n0l + cn * 8 + 2 * t;
        #pragma unroll
        for (int jj = 0; jj < 2; jj++) {
            int gm = jj ? gm1 : gm0;
            float c0 = acc[cn][2 * jj], c1 = acc[cn][2 * jj + 1];
            float u0 = g_u[gm * 64 + col],     hn0 = g_hn[gm * 64 + col];
            float u1 = g_u[gm * 64 + col + 1], hn1 = g_hn[gm * 64 + col + 1];
            out[gm * 64 + col]     = (1.f - u0) * hn0 + u0 * tanhf(c0);
            out[gm * 64 + col + 1] = (1.f - u1) * hn1 + u1 * tanhf(c1);
        }
    }
}

// ---------------- launch ----------------
extern "C" void kernel_launch(void* const* d_in, const int* in_sizes, int n_in,
                              void* d_out, int out_size) {
    const float* x   = (const float*)d_in[0];
    const float* h   = (const float*)d_in[1];
    const float* qv  = (const float*)d_in[2];
    const int*   adj = (const int*)  d_in[3];
    const int*   nb  = (const int*)  d_in[4];
    const int*   nn  = (const int*)  d_in[5];
    const float* Wq  = (const float*)d_in[6];
    const float* bq  = (const float*)d_in[7];
    const float* Wk  = (const float*)d_in[8];
    const float* bk  = (const float*)d_in[9];
    const float* Wv  = (const float*)d_in[10];
    const float* bv  = (const float*)d_in[11];
    const float* W1  = (const float*)d_in[12];
    const float* b1  = (const float*)d_in[13];
    const float* W2  = (const float*)d_in[14];
    const float* b2  = (const float*)d_in[15];
    const float* Wr  = (const float*)d_in[16];
    const float* br  = (const float*)d_in[17];
    const float* Wu  = (const float*)d_in[18];
    const float* bu  = (const float*)d_in[19];
    const float* Wc  = (const float*)d_in[20];
    const float* bc  = (const float*)d_in[21];
    float* out = (float*)d_out;

    const int SZ_RU = (32 * 132 + 32 * 33 + 2 * 2 * 129 * 36 + 2 * 32 * 34 + 16) * 4;
    const int SZ_C  = (32 * 132 + 32 * 33 + 2 * 129 * 36 + 32 * 34 + 16) * 4;

    cudaFuncSetAttribute(k_qkv,      cudaFuncAttributeMaxDynamicSharedMemorySize, SMEM_QKV);
    cudaFuncSetAttribute(k_attn_mma, cudaFuncAttributeMaxDynamicSharedMemorySize, SMEM_ATT);
    cudaFuncSetAttribute(k_mlp,      cudaFuncAttributeMaxDynamicSharedMemorySize, SMEM_MLP);
    cudaFuncSetAttribute(k_gate_ru,  cudaFuncAttributeMaxDynamicSharedMemorySize, SZ_RU);
    cudaFuncSetAttribute(k_gate_c,   cudaFuncAttributeMaxDynamicSharedMemorySize, SZ_C);

    k_adjpack<<<(Nn * Nn) / 256, 256>>>(adj);
    k_wprep<<<(5 * 129 * 132 + 255) / 256, 256>>>(W1, W2);
    k_qkv<<<dim3(128, 4), 256, SMEM_QKV>>>(x, h, Wv, bv, Wq, bq, Wk, bk);
    k_attn_mma<<<dim3(16, 8, 4), 128, SMEM_ATT>>>();
    k_mlp<<<256, 256, SMEM_MLP>>>(b1, b2);
    k_gate_ru<<<dim3(128, 2), 256, SZ_RU>>>(qv, nb, nn, Wr, br, Wu, bu, x, h);
    k_gate_c<<<dim3(128, 2), 128, SZ_C>>>(qv, Wc, bc, out);
}